// round 4
// baseline (speedup 1.0000x reference)
#include <cuda_runtime.h>
#include <math.h>

#define H    1024
#define NTOK 16384   // B*S
#define NH   16
#define HD   64

// ---------------- scratch (static device globals; no allocation) ----------------
__device__ float g_w[4ull * H * H];          // fused (LM@RM + W) * F  per proj (16 MB)
__device__ float g_qkv[3ull * NTOK * H];     // q,k,v (192 MB)
__device__ float g_ctx[(size_t)NTOK * H];    // attention context (64 MB)

// ---------------- weight reconstruction: w[o,i] = (LM@RM + W)[o,i] * F[o] ----------------
__global__ __launch_bounds__(256) void recon_kernel(
    const float* __restrict__ W, const float* __restrict__ LM,
    const float* __restrict__ RM, const float* __restrict__ F,
    float* __restrict__ wout)
{
    __shared__ float lms[16 * 64];
    const int o0 = blockIdx.y * 16;
    const int i  = blockIdx.x * 256 + threadIdx.x;
    for (int t = threadIdx.x; t < 16 * 64; t += 256) lms[t] = LM[o0 * 64 + t];
    __syncthreads();
    float acc[16];
#pragma unroll
    for (int j = 0; j < 16; j++) acc[j] = 0.f;
    for (int k = 0; k < 64; k++) {
        float rm = RM[k * H + i];
#pragma unroll
        for (int j = 0; j < 16; j++) acc[j] = fmaf(lms[j * 64 + k], rm, acc[j]);
    }
#pragma unroll
    for (int j = 0; j < 16; j++) {
        int o = o0 + j;
        wout[(size_t)o * H + i] = (acc[j] + W[(size_t)o * H + i]) * F[o];
    }
}

// ---------------- SGEMM: C[n,o] = sum_i A[n,i]*Bw[o,i] + bias[o]*F[o] ----------------
// 128x128 tile, K-tile 8, 256 threads, 8x8 per thread (split 4+4 fragments).
__global__ __launch_bounds__(256) void gemm_kernel(
    const float* __restrict__ A, const float* __restrict__ Bw,
    const float* __restrict__ bias, const float* __restrict__ F,
    float* __restrict__ C)
{
    __shared__ float As[8][128];
    __shared__ float Bs[8][128];
    const int tid = threadIdx.x;
    const int tx = tid & 15, ty = tid >> 4;
    const int bm = blockIdx.y * 128, bn = blockIdx.x * 128;
    const int lr = tid >> 1;          // 0..127
    const int lc = (tid & 1) * 4;     // 0 or 4
    const float* Ag = A  + (size_t)(bm + lr) * H + lc;
    const float* Bg = Bw + (size_t)(bn + lr) * H + lc;

    float acc[8][8];
#pragma unroll
    for (int i = 0; i < 8; i++)
#pragma unroll
        for (int j = 0; j < 8; j++) acc[i][j] = 0.f;

    for (int k0 = 0; k0 < H; k0 += 8) {
        float4 a4 = *(const float4*)(Ag + k0);
        float4 b4 = *(const float4*)(Bg + k0);
        __syncthreads();
        As[lc + 0][lr] = a4.x; As[lc + 1][lr] = a4.y;
        As[lc + 2][lr] = a4.z; As[lc + 3][lr] = a4.w;
        Bs[lc + 0][lr] = b4.x; Bs[lc + 1][lr] = b4.y;
        Bs[lc + 2][lr] = b4.z; Bs[lc + 3][lr] = b4.w;
        __syncthreads();
#pragma unroll
        for (int k = 0; k < 8; k++) {
            float4 a0 = *(const float4*)&As[k][ty * 4];
            float4 a1 = *(const float4*)&As[k][64 + ty * 4];
            float4 b0 = *(const float4*)&Bs[k][tx * 4];
            float4 b1 = *(const float4*)&Bs[k][64 + tx * 4];
            float av[8] = {a0.x, a0.y, a0.z, a0.w, a1.x, a1.y, a1.z, a1.w};
            float bv[8] = {b0.x, b0.y, b0.z, b0.w, b1.x, b1.y, b1.z, b1.w};
#pragma unroll
            for (int i = 0; i < 8; i++)
#pragma unroll
                for (int j = 0; j < 8; j++)
                    acc[i][j] = fmaf(av[i], bv[j], acc[i][j]);
        }
    }

    float bf[8];
#pragma unroll
    for (int j = 0; j < 8; j++) {
        int col = bn + ((j < 4) ? tx * 4 + j : 64 + tx * 4 + (j - 4));
        bf[j] = bias[col] * F[col];
    }
#pragma unroll
    for (int i = 0; i < 8; i++) {
        int row = bm + ((i < 4) ? ty * 4 + i : 64 + ty * 4 + (i - 4));
        float4 o0 = make_float4(acc[i][0] + bf[0], acc[i][1] + bf[1],
                                acc[i][2] + bf[2], acc[i][3] + bf[3]);
        float4 o1 = make_float4(acc[i][4] + bf[4], acc[i][5] + bf[5],
                                acc[i][6] + bf[6], acc[i][7] + bf[7]);
        *(float4*)&C[(size_t)row * H + bn + tx * 4]      = o0;
        *(float4*)&C[(size_t)row * H + bn + 64 + tx * 4] = o1;
    }
}

// ---------------- Flash attention: per (b,h), 128x128 tiles, online softmax ----------------
#define VPAD 68
#define PPAD 132
#define OFF_Q 0
#define OFF_K (64 * 128)
#define OFF_V (2 * 64 * 128)
#define OFF_P (2 * 64 * 128 + 128 * VPAD)
#define ATT_SMEM ((2 * 64 * 128 + 128 * VPAD + 128 * PPAD) * 4)

extern __shared__ float smf[];

__global__ __launch_bounds__(256) void attn_kernel(
    const float* __restrict__ Q, const float* __restrict__ K,
    const float* __restrict__ V, float* __restrict__ O)
{
    float* Qs = smf + OFF_Q;   // [d][row]  64x128
    float* Ks = smf + OFF_K;   // [d][col]  64x128
    float* Vs = smf + OFF_V;   // [k][d]    128x68 (padded)
    float* Ps = smf + OFF_P;   // [k][row]  128x132 (padded)
    const int tid = threadIdx.x;
    const int tx = tid & 15, ty = tid >> 4;
    const int qt = blockIdx.x, hh = blockIdx.y, b = blockIdx.z;
    const int lr = tid >> 1;          // 0..127
    const int d0 = (tid & 1) * 32;

    // load Q tile transposed with 1/sqrt(hd) folded in
    {
        int s = qt * 128 + lr;
        const float* gq = Q + ((size_t)(b * 1024 + s)) * H + hh * HD + d0;
#pragma unroll
        for (int c = 0; c < 8; c++) {
            float4 vq = *(const float4*)(gq + c * 4);
            Qs[(d0 + c * 4 + 0) * 128 + lr] = vq.x * 0.125f;
            Qs[(d0 + c * 4 + 1) * 128 + lr] = vq.y * 0.125f;
            Qs[(d0 + c * 4 + 2) * 128 + lr] = vq.z * 0.125f;
            Qs[(d0 + c * 4 + 3) * 128 + lr] = vq.w * 0.125f;
        }
    }

    float m_i[8], l_i[8], oa[8][4];
#pragma unroll
    for (int i = 0; i < 8; i++) {
        m_i[i] = -3.0e38f; l_i[i] = 0.f;
#pragma unroll
        for (int j = 0; j < 4; j++) oa[i][j] = 0.f;
    }

    for (int kt = 0; kt < 8; kt++) {
        __syncthreads();   // prior PV reads of Ks/Vs done
        {
            int s = kt * 128 + lr;
            const float* gk = K + ((size_t)(b * 1024 + s)) * H + hh * HD + d0;
            const float* gv = V + ((size_t)(b * 1024 + s)) * H + hh * HD + d0;
#pragma unroll
            for (int c = 0; c < 8; c++) {
                float4 vk = *(const float4*)(gk + c * 4);
                Ks[(d0 + c * 4 + 0) * 128 + lr] = vk.x;
                Ks[(d0 + c * 4 + 1) * 128 + lr] = vk.y;
                Ks[(d0 + c * 4 + 2) * 128 + lr] = vk.z;
                Ks[(d0 + c * 4 + 3) * 128 + lr] = vk.w;
                float4 vv = *(const float4*)(gv + c * 4);
                *(float4*)&Vs[lr * VPAD + d0 + c * 4] = vv;
            }
        }
        __syncthreads();

        // S = Q K^T (scaled)
        float sa[8][8];
#pragma unroll
        for (int i = 0; i < 8; i++)
#pragma unroll
            for (int j = 0; j < 8; j++) sa[i][j] = 0.f;
#pragma unroll 8
        for (int d = 0; d < 64; d++) {
            float4 a0 = *(const float4*)&Qs[d * 128 + ty * 4];
            float4 a1 = *(const float4*)&Qs[d * 128 + 64 + ty * 4];
            float4 b0 = *(const float4*)&Ks[d * 128 + tx * 4];
            float4 b1 = *(const float4*)&Ks[d * 128 + 64 + tx * 4];
            float av[8] = {a0.x, a0.y, a0.z, a0.w, a1.x, a1.y, a1.z, a1.w};
            float bv[8] = {b0.x, b0.y, b0.z, b0.w, b1.x, b1.y, b1.z, b1.w};
#pragma unroll
            for (int i = 0; i < 8; i++)
#pragma unroll
                for (int j = 0; j < 8; j++)
                    sa[i][j] = fmaf(av[i], bv[j], sa[i][j]);
        }

        // online softmax per row (row groups span 16 consecutive lanes)
#pragma unroll
        for (int i = 0; i < 8; i++) {
            float mx = sa[i][0];
#pragma unroll
            for (int j = 1; j < 8; j++) mx = fmaxf(mx, sa[i][j]);
#pragma unroll
            for (int off = 8; off; off >>= 1)
                mx = fmaxf(mx, __shfl_xor_sync(0xffffffffu, mx, off));
            float mnew = fmaxf(m_i[i], mx);
            float corr = __expf(m_i[i] - mnew);
            float rs = 0.f;
#pragma unroll
            for (int j = 0; j < 8; j++) {
                float p = __expf(sa[i][j] - mnew);
                sa[i][j] = p;
                rs += p;
            }
#pragma unroll
            for (int off = 8; off; off >>= 1)
                rs += __shfl_xor_sync(0xffffffffu, rs, off);
            l_i[i] = l_i[i] * corr + rs;
            m_i[i] = mnew;
#pragma unroll
            for (int j = 0; j < 4; j++) oa[i][j] *= corr;
        }

        // stage P to smem (k-major with pad)
#pragma unroll
        for (int j = 0; j < 8; j++) {
            int c = (j < 4) ? tx * 4 + j : 64 + tx * 4 + (j - 4);
            *(float4*)&Ps[c * PPAD + ty * 4] =
                make_float4(sa[0][j], sa[1][j], sa[2][j], sa[3][j]);
            *(float4*)&Ps[c * PPAD + 64 + ty * 4] =
                make_float4(sa[4][j], sa[5][j], sa[6][j], sa[7][j]);
        }
        __syncthreads();

        // O += P V
#pragma unroll 4
        for (int kk = 0; kk < 128; kk++) {
            float4 p0 = *(const float4*)&Ps[kk * PPAD + ty * 4];
            float4 p1 = *(const float4*)&Ps[kk * PPAD + 64 + ty * 4];
            float4 vv = *(const float4*)&Vs[kk * VPAD + tx * 4];
            float pv[8] = {p0.x, p0.y, p0.z, p0.w, p1.x, p1.y, p1.z, p1.w};
            float vf[4] = {vv.x, vv.y, vv.z, vv.w};
#pragma unroll
            for (int i = 0; i < 8; i++)
#pragma unroll
                for (int j = 0; j < 4; j++)
                    oa[i][j] = fmaf(pv[i], vf[j], oa[i][j]);
        }
    }

    // normalize + write ctx
#pragma unroll
    for (int i = 0; i < 8; i++) {
        int r = (i < 4) ? ty * 4 + i : 64 + ty * 4 + (i - 4);
        int s = qt * 128 + r;
        float inv = 1.0f / l_i[i];
        float4 o4 = make_float4(oa[i][0] * inv, oa[i][1] * inv,
                                oa[i][2] * inv, oa[i][3] * inv);
        *(float4*)&O[((size_t)(b * 1024 + s)) * H + hh * HD + tx * 4] = o4;
    }
}

// ---------------- launcher ----------------
extern "C" void kernel_launch(void* const* d_in, const int* in_sizes, int n_in,
                              void* d_out, int out_size)
{
    const float* x = (const float*)d_in[0];
    float *w_all, *qkv, *ctx;
    cudaGetSymbolAddress((void**)&w_all, g_w);
    cudaGetSymbolAddress((void**)&qkv, g_qkv);
    cudaGetSymbolAddress((void**)&ctx, g_ctx);

    // Opt-in to >48KB dynamic smem; attribute persists, so only set outside capture.
    cudaStreamCaptureStatus cst = cudaStreamCaptureStatusNone;
    cudaStreamIsCapturing((cudaStream_t)0, &cst);
    if (cst == cudaStreamCaptureStatusNone) {
        cudaFuncSetAttribute(attn_kernel,
                             cudaFuncAttributeMaxDynamicSharedMemorySize, ATT_SMEM);
    }

    dim3 rg(4, 64);    // 1024/256 cols x 1024/16 rows
    dim3 gg(8, 128);   // N=1024/128, M=16384/128

    for (int p = 0; p < 4; p++) {
        const float* W  = (const float*)d_in[1 + p * 5 + 0];
        const float* LM = (const float*)d_in[1 + p * 5 + 2];
        const float* RM = (const float*)d_in[1 + p * 5 + 3];
        const float* F  = (const float*)d_in[1 + p * 5 + 4];
        recon_kernel<<<rg, 256>>>(W, LM, RM, F, w_all + (size_t)p * H * H);
    }
    for (int p = 0; p < 3; p++) {
        const float* bias = (const float*)d_in[1 + p * 5 + 1];
        const float* F    = (const float*)d_in[1 + p * 5 + 4];
        gemm_kernel<<<gg, 256>>>(x, w_all + (size_t)p * H * H, bias, F,
                                 qkv + (size_t)p * NTOK * H);
    }
    attn_kernel<<<dim3(8, NH, 16), 256, ATT_SMEM>>>(
        qkv, qkv + (size_t)NTOK * H, qkv + 2ull * NTOK * H, ctx);
    {
        const float* bias = (const float*)d_in[1 + 3 * 5 + 1];
        const float* F    = (const float*)d_in[1 + 3 * 5 + 4];
        gemm_kernel<<<gg, 256>>>(ctx, w_all + 3ull * H * H, bias, F, (float*)d_out);
    }
}

// round 11
// speedup vs baseline: 1.5661x; 1.5661x over previous
#include <cuda_runtime.h>
#include <cuda_bf16.h>
#include <math.h>
#include <stdint.h>

#define H    1024
#define NTOK 16384   // B*S
#define NH   16
#define HD   64
#define HH   (1024*1024)

// ---------------- scratch (static device globals; no allocation) ----------------
__device__ float g_qkv[3ull * NTOK * H];                    // q,k,v fp32 (192 MB)
__device__ __nv_bfloat16 g_wh[4ull * HH], g_wl[4ull * HH];  // weight hi/lo
__device__ __nv_bfloat16 g_xh[(size_t)NTOK * H], g_xl[(size_t)NTOK * H];
__device__ __nv_bfloat16 g_ch[(size_t)NTOK * H], g_cl[(size_t)NTOK * H];

// ---------------- PTX helpers (sm_80-era: valid on plain sm_103 target) ----------------
__device__ __forceinline__ uint32_t smem_u32(const void* p) {
    uint32_t a;
    asm("{ .reg .u64 t; cvta.to.shared.u64 t, %1; cvt.u32.u64 %0, t; }" : "=r"(a) : "l"(p));
    return a;
}
__device__ __forceinline__ void cp16(uint32_t dst, const void* src) {
    asm volatile("cp.async.cg.shared.global [%0], [%1], 16;" :: "r"(dst), "l"(src));
}
#define CP_COMMIT() asm volatile("cp.async.commit_group;" ::: "memory")
#define CP_WAIT(n)  asm volatile("cp.async.wait_group %0;" :: "n"(n) : "memory")

__device__ __forceinline__ void ldsm4(uint32_t* r, uint32_t addr) {
    asm volatile("ldmatrix.sync.aligned.m8n8.x4.shared.b16 {%0,%1,%2,%3}, [%4];"
        : "=r"(r[0]), "=r"(r[1]), "=r"(r[2]), "=r"(r[3]) : "r"(addr));
}
__device__ __forceinline__ void ldsm2(uint32_t* r, uint32_t addr) {
    asm volatile("ldmatrix.sync.aligned.m8n8.x2.shared.b16 {%0,%1}, [%2];"
        : "=r"(r[0]), "=r"(r[1]) : "r"(addr));
}
__device__ __forceinline__ void mma16816(float* d, const uint32_t* a, const uint32_t* b) {
    asm volatile(
        "mma.sync.aligned.m16n8k16.row.col.f32.bf16.bf16.f32 "
        "{%0,%1,%2,%3}, {%4,%5,%6,%7}, {%8,%9}, {%0,%1,%2,%3};"
        : "+f"(d[0]), "+f"(d[1]), "+f"(d[2]), "+f"(d[3])
        : "r"(a[0]), "r"(a[1]), "r"(a[2]), "r"(a[3]), "r"(b[0]), "r"(b[1]));
}

// ---------------- recon: w=(LM@RM+W)*F -> bf16 hi/lo ----------------
__global__ __launch_bounds__(256) void recon2_kernel(
    const float* __restrict__ W, const float* __restrict__ LM,
    const float* __restrict__ RM, const float* __restrict__ F,
    __nv_bfloat16* __restrict__ wh, __nv_bfloat16* __restrict__ wl)
{
    __shared__ float lms[16 * 64];
    const int o0 = blockIdx.y * 16;
    const int i  = blockIdx.x * 256 + threadIdx.x;
    for (int t = threadIdx.x; t < 16 * 64; t += 256) lms[t] = LM[o0 * 64 + t];
    __syncthreads();
    float acc[16];
#pragma unroll
    for (int j = 0; j < 16; j++) acc[j] = 0.f;
    for (int k = 0; k < 64; k++) {
        float rm = RM[k * H + i];
#pragma unroll
        for (int j = 0; j < 16; j++) acc[j] = fmaf(lms[j * 64 + k], rm, acc[j]);
    }
#pragma unroll
    for (int j = 0; j < 16; j++) {
        int o = o0 + j;
        float w = (acc[j] + W[(size_t)o * H + i]) * F[o];
        __nv_bfloat16 hi = __float2bfloat16(w);
        wh[(size_t)o * H + i] = hi;
        wl[(size_t)o * H + i] = __float2bfloat16(w - __bfloat162float(hi));
    }
}

// ---------------- x split: fp32 -> bf16 hi/lo ----------------
__global__ __launch_bounds__(256) void split_kernel(
    const float* __restrict__ x, __nv_bfloat16* __restrict__ xh,
    __nv_bfloat16* __restrict__ xl)
{
    size_t i = ((size_t)blockIdx.x * 256 + threadIdx.x) * 4;
    float4 v = *(const float4*)(x + i);
    float vv[4] = {v.x, v.y, v.z, v.w};
    __nv_bfloat16 h[4], l[4];
#pragma unroll
    for (int j = 0; j < 4; j++) {
        h[j] = __float2bfloat16(vv[j]);
        l[j] = __float2bfloat16(vv[j] - __bfloat162float(h[j]));
    }
    __nv_bfloat162 h01; h01.x = h[0]; h01.y = h[1];
    __nv_bfloat162 h23; h23.x = h[2]; h23.y = h[3];
    __nv_bfloat162 l01; l01.x = l[0]; l01.y = l[1];
    __nv_bfloat162 l23; l23.x = l[2]; l23.y = l[3];
    *reinterpret_cast<__nv_bfloat162*>(xh + i)     = h01;
    *reinterpret_cast<__nv_bfloat162*>(xh + i + 2) = h23;
    *reinterpret_cast<__nv_bfloat162*>(xl + i)     = l01;
    *reinterpret_cast<__nv_bfloat162*>(xl + i + 2) = l23;
}

// ---------------- mma.sync bf16 GEMM: C[n,o] = sum_i A[n,i]*Bw[o,i] + bias*F ----------------
// 3-pass split precision: C = Ah*Bh + Ah*Bl + Al*Bh. CTA 128x128, BK=32, 8 warps (2x4).
#define LDE 40                    // smem row stride, elems (32 + 8 pad)
#define TILE_B (128 * LDE * 2)    // 10240 bytes per sub-tile
#define STAGE_B (4 * TILE_B)      // Ah, Al, Bh, Bl = 40960 bytes
#define GEMM_SMEM (2 * STAGE_B + 512)
#define KSTAGES 32                // 1024 / 32

extern __shared__ float smf[];

__global__ __launch_bounds__(256, 1) void gemm_tc(
    const __nv_bfloat16* __restrict__ Ah, const __nv_bfloat16* __restrict__ Al,
    const __nv_bfloat16* __restrict__ Bh, const __nv_bfloat16* __restrict__ Bl,
    const float* __restrict__ bias, const float* __restrict__ F,
    float* __restrict__ C)
{
    char* smem = (char*)smf;
    const uint32_t sb = smem_u32(smem);
    float* bfs = (float*)(smem + 2 * STAGE_B);
    const int tid = threadIdx.x, wid = tid >> 5, lane = tid & 31;
    const int bm = blockIdx.y * 128, bn = blockIdx.x * 128;

    if (tid < 128) bfs[tid] = bias[bn + tid] * F[bn + tid];

    const char* gA_h = (const char*)Ah + (size_t)bm * 2048;
    const char* gA_l = (const char*)Al + (size_t)bm * 2048;
    const char* gB_h = (const char*)Bh + (size_t)bn * 2048;
    const char* gB_l = (const char*)Bl + (size_t)bn * 2048;

    auto load_stage = [&](int s) {
        uint32_t st = sb + (uint32_t)(s & 1) * STAGE_B;
        size_t kb = (size_t)s * 64;          // BK=32 elems = 64 bytes
#pragma unroll
        for (int it = 0; it < 2; it++) {
            int i = it * 256 + tid;          // 0..511
            int r = i >> 2, c = i & 3;
            uint32_t off = (uint32_t)(r * (LDE * 2) + c * 16);
            size_t g = (size_t)r * 2048 + kb + c * 16;
            cp16(st + 0 * TILE_B + off, gA_h + g);
            cp16(st + 1 * TILE_B + off, gA_l + g);
            cp16(st + 2 * TILE_B + off, gB_h + g);
            cp16(st + 3 * TILE_B + off, gB_l + g);
        }
    };

    float acc[16][4];
#pragma unroll
    for (int i = 0; i < 16; i++)
#pragma unroll
        for (int j = 0; j < 4; j++) acc[i][j] = 0.f;

    const int warp_m = (wid >> 2) * 64;      // 0 or 64
    const int warp_n = (wid & 3) * 32;       // 0,32,64,96
    const uint32_t a_row = warp_m + (lane & 15);
    const uint32_t a_k8  = (lane >> 4) * 8;
    const uint32_t b_row = warp_n + (lane & 7);
    const uint32_t b_k8  = ((lane >> 3) & 1) * 8;

    load_stage(0);
    CP_COMMIT();

    for (int s = 0; s < KSTAGES; s++) {
        if (s + 1 < KSTAGES) {
            load_stage(s + 1);
            CP_COMMIT();
            CP_WAIT(1);
        } else {
            CP_WAIT(0);
        }
        __syncthreads();

        uint32_t st = sb + (uint32_t)(s & 1) * STAGE_B;
#pragma unroll
        for (int kk = 0; kk < 32; kk += 16) {
            uint32_t ah[4][4], al[4][4], bh[4][2], bl[4][2];
#pragma unroll
            for (int mi = 0; mi < 4; mi++) {
                uint32_t ao = ((a_row + mi * 16) * LDE + kk + a_k8) * 2;
                ldsm4(ah[mi], st + 0 * TILE_B + ao);
                ldsm4(al[mi], st + 1 * TILE_B + ao);
            }
#pragma unroll
            for (int ni = 0; ni < 4; ni++) {
                uint32_t bo = ((b_row + ni * 8) * LDE + kk + b_k8) * 2;
                ldsm2(bh[ni], st + 2 * TILE_B + bo);
                ldsm2(bl[ni], st + 3 * TILE_B + bo);
            }
#pragma unroll
            for (int mi = 0; mi < 4; mi++)
#pragma unroll
                for (int ni = 0; ni < 4; ni++) {
                    mma16816(acc[mi * 4 + ni], ah[mi], bh[ni]);
                    mma16816(acc[mi * 4 + ni], ah[mi], bl[ni]);
                    mma16816(acc[mi * 4 + ni], al[mi], bh[ni]);
                }
        }
        __syncthreads();
    }

    // epilogue: direct coalesced float2 stores
    const int rbase = warp_m + (lane >> 2);
    const int cbase = warp_n + (lane & 3) * 2;
#pragma unroll
    for (int mi = 0; mi < 4; mi++)
#pragma unroll
        for (int ni = 0; ni < 4; ni++) {
            const float* a4 = acc[mi * 4 + ni];
            int c = cbase + ni * 8;
            float bf0 = bfs[c], bf1 = bfs[c + 1];
            int r0 = bm + rbase + mi * 16;
            *(float2*)&C[(size_t)r0 * H + bn + c] =
                make_float2(a4[0] + bf0, a4[1] + bf1);
            *(float2*)&C[(size_t)(r0 + 8) * H + bn + c] =
                make_float2(a4[2] + bf0, a4[3] + bf1);
        }
}

// ---------------- Flash attention (fp32), writes bf16 hi/lo ctx ----------------
#define VPAD 68
#define PPAD 132
#define OFF_Q 0
#define OFF_K (64 * 128)
#define OFF_V (2 * 64 * 128)
#define OFF_P (2 * 64 * 128 + 128 * VPAD)
#define ATT_SMEM ((2 * 64 * 128 + 128 * VPAD + 128 * PPAD) * 4)

__global__ __launch_bounds__(256) void attn_kernel(
    const float* __restrict__ Q, const float* __restrict__ K,
    const float* __restrict__ V, __nv_bfloat16* __restrict__ Ch,
    __nv_bfloat16* __restrict__ Cl)
{
    float* Qs = smf + OFF_Q;
    float* Ks = smf + OFF_K;
    float* Vs = smf + OFF_V;
    float* Ps = smf + OFF_P;
    const int tid = threadIdx.x;
    const int tx = tid & 15, ty = tid >> 4;
    const int qt = blockIdx.x, hh = blockIdx.y, b = blockIdx.z;
    const int lr = tid >> 1;
    const int d0 = (tid & 1) * 32;

    {
        int s = qt * 128 + lr;
        const float* gq = Q + ((size_t)(b * 1024 + s)) * H + hh * HD + d0;
#pragma unroll
        for (int c = 0; c < 8; c++) {
            float4 vq = *(const float4*)(gq + c * 4);
            Qs[(d0 + c * 4 + 0) * 128 + lr] = vq.x * 0.125f;
            Qs[(d0 + c * 4 + 1) * 128 + lr] = vq.y * 0.125f;
            Qs[(d0 + c * 4 + 2) * 128 + lr] = vq.z * 0.125f;
            Qs[(d0 + c * 4 + 3) * 128 + lr] = vq.w * 0.125f;
        }
    }

    float m_i[8], l_i[8], oa[8][4];
#pragma unroll
    for (int i = 0; i < 8; i++) {
        m_i[i] = -3.0e38f; l_i[i] = 0.f;
#pragma unroll
        for (int j = 0; j < 4; j++) oa[i][j] = 0.f;
    }

    for (int kt = 0; kt < 8; kt++) {
        __syncthreads();
        {
            int s = kt * 128 + lr;
            const float* gk = K + ((size_t)(b * 1024 + s)) * H + hh * HD + d0;
            const float* gv = V + ((size_t)(b * 1024 + s)) * H + hh * HD + d0;
#pragma unroll
            for (int c = 0; c < 8; c++) {
                float4 vk = *(const float4*)(gk + c * 4);
                Ks[(d0 + c * 4 + 0) * 128 + lr] = vk.x;
                Ks[(d0 + c * 4 + 1) * 128 + lr] = vk.y;
                Ks[(d0 + c * 4 + 2) * 128 + lr] = vk.z;
                Ks[(d0 + c * 4 + 3) * 128 + lr] = vk.w;
                float4 vv = *(const float4*)(gv + c * 4);
                *(float4*)&Vs[lr * VPAD + d0 + c * 4] = vv;
            }
        }
        __syncthreads();

        float sa[8][8];
#pragma unroll
        for (int i = 0; i < 8; i++)
#pragma unroll
            for (int j = 0; j < 8; j++) sa[i][j] = 0.f;
#pragma unroll 8
        for (int d = 0; d < 64; d++) {
            float4 a0 = *(const float4*)&Qs[d * 128 + ty * 4];
            float4 a1 = *(const float4*)&Qs[d * 128 + 64 + ty * 4];
            float4 b0 = *(const float4*)&Ks[d * 128 + tx * 4];
            float4 b1 = *(const float4*)&Ks[d * 128 + 64 + tx * 4];
            float av[8] = {a0.x, a0.y, a0.z, a0.w, a1.x, a1.y, a1.z, a1.w};
            float bv[8] = {b0.x, b0.y, b0.z, b0.w, b1.x, b1.y, b1.z, b1.w};
#pragma unroll
            for (int i = 0; i < 8; i++)
#pragma unroll
                for (int j = 0; j < 8; j++)
                    sa[i][j] = fmaf(av[i], bv[j], sa[i][j]);
        }

#pragma unroll
        for (int i = 0; i < 8; i++) {
            float mx = sa[i][0];
#pragma unroll
            for (int j = 1; j < 8; j++) mx = fmaxf(mx, sa[i][j]);
#pragma unroll
            for (int off = 8; off; off >>= 1)
                mx = fmaxf(mx, __shfl_xor_sync(0xffffffffu, mx, off));
            float mnew = fmaxf(m_i[i], mx);
            float corr = __expf(m_i[i] - mnew);
            float rs = 0.f;
#pragma unroll
            for (int j = 0; j < 8; j++) {
                float p = __expf(sa[i][j] - mnew);
                sa[i][j] = p;
                rs += p;
            }
#pragma unroll
            for (int off = 8; off; off >>= 1)
                rs += __shfl_xor_sync(0xffffffffu, rs, off);
            l_i[i] = l_i[i] * corr + rs;
            m_i[i] = mnew;
#pragma unroll
            for (int j = 0; j < 4; j++) oa[i][j] *= corr;
        }

#pragma unroll
        for (int j = 0; j < 8; j++) {
            int c = (j < 4) ? tx * 4 + j : 64 + tx * 4 + (j - 4);
            *(float4*)&Ps[c * PPAD + ty * 4] =
                make_float4(sa[0][j], sa[1][j], sa[2][j], sa[3][j]);
            *(float4*)&Ps[c * PPAD + 64 + ty * 4] =
                make_float4(sa[4][j], sa[5][j], sa[6][j], sa[7][j]);
        }
        __syncthreads();

#pragma unroll 4
        for (int kk = 0; kk < 128; kk++) {
            float4 p0 = *(const float4*)&Ps[kk * PPAD + ty * 4];
            float4 p1 = *(const float4*)&Ps[kk * PPAD + 64 + ty * 4];
            float4 vv = *(const float4*)&Vs[kk * VPAD + tx * 4];
            float pv[8] = {p0.x, p0.y, p0.z, p0.w, p1.x, p1.y, p1.z, p1.w};
            float vf[4] = {vv.x, vv.y, vv.z, vv.w};
#pragma unroll
            for (int i = 0; i < 8; i++)
#pragma unroll
                for (int j = 0; j < 4; j++)
                    oa[i][j] = fmaf(pv[i], vf[j], oa[i][j]);
        }
    }

#pragma unroll
    for (int i = 0; i < 8; i++) {
        int r = (i < 4) ? ty * 4 + i : 64 + ty * 4 + (i - 4);
        int s = qt * 128 + r;
        float inv = 1.0f / l_i[i];
        float vals[4] = {oa[i][0] * inv, oa[i][1] * inv, oa[i][2] * inv, oa[i][3] * inv};
        __nv_bfloat16 h[4], l[4];
#pragma unroll
        for (int j = 0; j < 4; j++) {
            h[j] = __float2bfloat16(vals[j]);
            l[j] = __float2bfloat16(vals[j] - __bfloat162float(h[j]));
        }
        size_t obase = ((size_t)(b * 1024 + s)) * H + hh * HD + tx * 4;
        __nv_bfloat162 h01; h01.x = h[0]; h01.y = h[1];
        __nv_bfloat162 h23; h23.x = h[2]; h23.y = h[3];
        __nv_bfloat162 l01; l01.x = l[0]; l01.y = l[1];
        __nv_bfloat162 l23; l23.x = l[2]; l23.y = l[3];
        *reinterpret_cast<__nv_bfloat162*>(&Ch[obase])     = h01;
        *reinterpret_cast<__nv_bfloat162*>(&Ch[obase + 2]) = h23;
        *reinterpret_cast<__nv_bfloat162*>(&Cl[obase])     = l01;
        *reinterpret_cast<__nv_bfloat162*>(&Cl[obase + 2]) = l23;
    }
}

// ---------------- launcher ----------------
extern "C" void kernel_launch(void* const* d_in, const int* in_sizes, int n_in,
                              void* d_out, int out_size)
{
    const float* x = (const float*)d_in[0];
    float* qkv;
    __nv_bfloat16 *wh, *wl, *xh, *xl, *ch, *cl;
    cudaGetSymbolAddress((void**)&qkv, g_qkv);
    cudaGetSymbolAddress((void**)&wh, g_wh);
    cudaGetSymbolAddress((void**)&wl, g_wl);
    cudaGetSymbolAddress((void**)&xh, g_xh);
    cudaGetSymbolAddress((void**)&xl, g_xl);
    cudaGetSymbolAddress((void**)&ch, g_ch);
    cudaGetSymbolAddress((void**)&cl, g_cl);

    cudaStreamCaptureStatus cst = cudaStreamCaptureStatusNone;
    cudaError_t qerr = cudaStreamIsCapturing((cudaStream_t)0, &cst);
    if (qerr != cudaSuccess || cst != cudaStreamCaptureStatusActive) {
        cudaFuncSetAttribute(attn_kernel,
                             cudaFuncAttributeMaxDynamicSharedMemorySize, ATT_SMEM);
        cudaFuncSetAttribute(gemm_tc,
                             cudaFuncAttributeMaxDynamicSharedMemorySize, GEMM_SMEM);
    }

    dim3 rg(4, 64);     // recon grid
    dim3 gg(8, 128);    // gemm: 8 N-tiles x 128 M-tiles

    for (int p = 0; p < 4; p++) {
        const float* W  = (const float*)d_in[1 + p * 5 + 0];
        const float* LM = (const float*)d_in[1 + p * 5 + 2];
        const float* RM = (const float*)d_in[1 + p * 5 + 3];
        const float* F  = (const float*)d_in[1 + p * 5 + 4];
        recon2_kernel<<<rg, 256>>>(W, LM, RM, F, wh + (size_t)p * HH, wl + (size_t)p * HH);
    }
    split_kernel<<<(NTOK * H) / 1024, 256>>>(x, xh, xl);

    for (int p = 0; p < 3; p++) {
        const float* bias = (const float*)d_in[1 + p * 5 + 1];
        const float* F    = (const float*)d_in[1 + p * 5 + 4];
        gemm_tc<<<gg, 256, GEMM_SMEM>>>(xh, xl, wh + (size_t)p * HH, wl + (size_t)p * HH,
                                        bias, F, qkv + (size_t)p * NTOK * H);
    }
    attn_kernel<<<dim3(8, NH, 16), 256, ATT_SMEM>>>(
        qkv, qkv + (size_t)NTOK * H, qkv + 2ull * NTOK * H, ch, cl);
    {
        const float* bias = (const float*)d_in[1 + 3 * 5 + 1];
        const float* F    = (const float*)d_in[1 + 3 * 5 + 4];
        gemm_tc<<<gg, 256, GEMM_SMEM>>>(ch, cl, wh + 3ull * HH, wl + 3ull * HH,
                                        bias, F, (float*)d_out);
    }
}

// round 12
// speedup vs baseline: 1.7495x; 1.1171x over previous
#include <cuda_runtime.h>
#include <cuda_bf16.h>
#include <math.h>
#include <stdint.h>

#define H    1024
#define NTOK 16384   // B*S
#define NH   16
#define HD   64
#define HH   (1024*1024)

// ---------------- scratch (static device globals; no allocation) ----------------
__device__ __nv_bfloat16 g_wh[4ull * HH], g_wl[4ull * HH];        // weight hi/lo
__device__ __nv_bfloat16 g_xh[(size_t)NTOK * H], g_xl[(size_t)NTOK * H];
__device__ __nv_bfloat16 g_qkvh[3ull * NTOK * H], g_qkvl[3ull * NTOK * H];
__device__ __nv_bfloat16 g_ch[(size_t)NTOK * H], g_cl[(size_t)NTOK * H];

// ---------------- PTX helpers (sm_80-era: valid on plain sm_103 target) ----------------
__device__ __forceinline__ uint32_t smem_u32(const void* p) {
    uint32_t a;
    asm("{ .reg .u64 t; cvta.to.shared.u64 t, %1; cvt.u32.u64 %0, t; }" : "=r"(a) : "l"(p));
    return a;
}
__device__ __forceinline__ void cp16(uint32_t dst, const void* src) {
    asm volatile("cp.async.cg.shared.global [%0], [%1], 16;" :: "r"(dst), "l"(src));
}
#define CP_COMMIT() asm volatile("cp.async.commit_group;" ::: "memory")
#define CP_WAIT(n)  asm volatile("cp.async.wait_group %0;" :: "n"(n) : "memory")

__device__ __forceinline__ void ldsm4(uint32_t* r, uint32_t addr) {
    asm volatile("ldmatrix.sync.aligned.m8n8.x4.shared.b16 {%0,%1,%2,%3}, [%4];"
        : "=r"(r[0]), "=r"(r[1]), "=r"(r[2]), "=r"(r[3]) : "r"(addr));
}
__device__ __forceinline__ void ldsm2(uint32_t* r, uint32_t addr) {
    asm volatile("ldmatrix.sync.aligned.m8n8.x2.shared.b16 {%0,%1}, [%2];"
        : "=r"(r[0]), "=r"(r[1]) : "r"(addr));
}
__device__ __forceinline__ void ldsm2t(uint32_t* r, uint32_t addr) {
    asm volatile("ldmatrix.sync.aligned.m8n8.x2.trans.shared.b16 {%0,%1}, [%2];"
        : "=r"(r[0]), "=r"(r[1]) : "r"(addr));
}
__device__ __forceinline__ void mma16816(float* d, const uint32_t* a, const uint32_t* b) {
    asm volatile(
        "mma.sync.aligned.m16n8k16.row.col.f32.bf16.bf16.f32 "
        "{%0,%1,%2,%3}, {%4,%5,%6,%7}, {%8,%9}, {%0,%1,%2,%3};"
        : "+f"(d[0]), "+f"(d[1]), "+f"(d[2]), "+f"(d[3])
        : "r"(a[0]), "r"(a[1]), "r"(a[2]), "r"(a[3]), "r"(b[0]), "r"(b[1]));
}
__device__ __forceinline__ void split2(float v0, float v1, uint32_t& hi, uint32_t& lo) {
    __nv_bfloat162 h = __float22bfloat162_rn(make_float2(v0, v1));
    float2 back = __bfloat1622float2(h);
    __nv_bfloat162 l = __float22bfloat162_rn(make_float2(v0 - back.x, v1 - back.y));
    hi = *reinterpret_cast<uint32_t*>(&h);
    lo = *reinterpret_cast<uint32_t*>(&l);
}

// ---------------- recon: w=(LM@RM+W)*F -> bf16 hi/lo ----------------
__global__ __launch_bounds__(256) void recon2_kernel(
    const float* __restrict__ W, const float* __restrict__ LM,
    const float* __restrict__ RM, const float* __restrict__ F,
    __nv_bfloat16* __restrict__ wh, __nv_bfloat16* __restrict__ wl)
{
    __shared__ float lms[16 * 64];
    const int o0 = blockIdx.y * 16;
    const int i  = blockIdx.x * 256 + threadIdx.x;
    for (int t = threadIdx.x; t < 16 * 64; t += 256) lms[t] = LM[o0 * 64 + t];
    __syncthreads();
    float acc[16];
#pragma unroll
    for (int j = 0; j < 16; j++) acc[j] = 0.f;
    for (int k = 0; k < 64; k++) {
        float rm = RM[k * H + i];
#pragma unroll
        for (int j = 0; j < 16; j++) acc[j] = fmaf(lms[j * 64 + k], rm, acc[j]);
    }
#pragma unroll
    for (int j = 0; j < 16; j++) {
        int o = o0 + j;
        float w = (acc[j] + W[(size_t)o * H + i]) * F[o];
        __nv_bfloat16 hi = __float2bfloat16(w);
        wh[(size_t)o * H + i] = hi;
        wl[(size_t)o * H + i] = __float2bfloat16(w - __bfloat162float(hi));
    }
}

// ---------------- x split: fp32 -> bf16 hi/lo ----------------
__global__ __launch_bounds__(256) void split_kernel(
    const float* __restrict__ x, __nv_bfloat16* __restrict__ xh,
    __nv_bfloat16* __restrict__ xl)
{
    size_t i = ((size_t)blockIdx.x * 256 + threadIdx.x) * 4;
    float4 v = *(const float4*)(x + i);
    uint32_t h01, l01, h23, l23;
    split2(v.x, v.y, h01, l01);
    split2(v.z, v.w, h23, l23);
    *reinterpret_cast<uint32_t*>(xh + i)     = h01;
    *reinterpret_cast<uint32_t*>(xh + i + 2) = h23;
    *reinterpret_cast<uint32_t*>(xl + i)     = l01;
    *reinterpret_cast<uint32_t*>(xl + i + 2) = l23;
}

// ---------------- mma.sync bf16 GEMM: C[n,o] = sum_i A[n,i]*Bw[o,i] + bias*F ----------------
// 3-pass split precision. CTA 128x128, BK=32, 8 warps (2x4).
// Output: fp32 (Cf) or bf16 hi/lo (Ch/Cl) if Ch != nullptr.
#define LDE 40
#define TILE_B (128 * LDE * 2)
#define STAGE_B (4 * TILE_B)
#define GEMM_SMEM (2 * STAGE_B + 512)
#define KSTAGES 32

extern __shared__ float smf[];

__global__ __launch_bounds__(256, 1) void gemm_tc(
    const __nv_bfloat16* __restrict__ Ah, const __nv_bfloat16* __restrict__ Al,
    const __nv_bfloat16* __restrict__ Bh, const __nv_bfloat16* __restrict__ Bl,
    const float* __restrict__ bias, const float* __restrict__ F,
    float* __restrict__ Cf, __nv_bfloat16* __restrict__ Ch,
    __nv_bfloat16* __restrict__ Cl)
{
    char* smem = (char*)smf;
    const uint32_t sb = smem_u32(smem);
    float* bfs = (float*)(smem + 2 * STAGE_B);
    const int tid = threadIdx.x, wid = tid >> 5, lane = tid & 31;
    const int bm = blockIdx.y * 128, bn = blockIdx.x * 128;

    if (tid < 128) bfs[tid] = bias[bn + tid] * F[bn + tid];

    const char* gA_h = (const char*)Ah + (size_t)bm * 2048;
    const char* gA_l = (const char*)Al + (size_t)bm * 2048;
    const char* gB_h = (const char*)Bh + (size_t)bn * 2048;
    const char* gB_l = (const char*)Bl + (size_t)bn * 2048;

    auto load_stage = [&](int s) {
        uint32_t st = sb + (uint32_t)(s & 1) * STAGE_B;
        size_t kb = (size_t)s * 64;
#pragma unroll
        for (int it = 0; it < 2; it++) {
            int i = it * 256 + tid;
            int r = i >> 2, c = i & 3;
            uint32_t off = (uint32_t)(r * (LDE * 2) + c * 16);
            size_t g = (size_t)r * 2048 + kb + c * 16;
            cp16(st + 0 * TILE_B + off, gA_h + g);
            cp16(st + 1 * TILE_B + off, gA_l + g);
            cp16(st + 2 * TILE_B + off, gB_h + g);
            cp16(st + 3 * TILE_B + off, gB_l + g);
        }
    };

    float acc[16][4];
#pragma unroll
    for (int i = 0; i < 16; i++)
#pragma unroll
        for (int j = 0; j < 4; j++) acc[i][j] = 0.f;

    const int warp_m = (wid >> 2) * 64;
    const int warp_n = (wid & 3) * 32;
    const uint32_t a_row = warp_m + (lane & 15);
    const uint32_t a_k8  = (lane >> 4) * 8;
    const uint32_t b_row = warp_n + (lane & 7);
    const uint32_t b_k8  = ((lane >> 3) & 1) * 8;

    load_stage(0);
    CP_COMMIT();

    for (int s = 0; s < KSTAGES; s++) {
        if (s + 1 < KSTAGES) {
            load_stage(s + 1);
            CP_COMMIT();
            CP_WAIT(1);
        } else {
            CP_WAIT(0);
        }
        __syncthreads();

        uint32_t st = sb + (uint32_t)(s & 1) * STAGE_B;
#pragma unroll
        for (int kk = 0; kk < 32; kk += 16) {
            uint32_t ah[4][4], al[4][4], bh[4][2], bl[4][2];
#pragma unroll
            for (int mi = 0; mi < 4; mi++) {
                uint32_t ao = ((a_row + mi * 16) * LDE + kk + a_k8) * 2;
                ldsm4(ah[mi], st + 0 * TILE_B + ao);
                ldsm4(al[mi], st + 1 * TILE_B + ao);
            }
#pragma unroll
            for (int ni = 0; ni < 4; ni++) {
                uint32_t bo = ((b_row + ni * 8) * LDE + kk + b_k8) * 2;
                ldsm2(bh[ni], st + 2 * TILE_B + bo);
                ldsm2(bl[ni], st + 3 * TILE_B + bo);
            }
#pragma unroll
            for (int mi = 0; mi < 4; mi++)
#pragma unroll
                for (int ni = 0; ni < 4; ni++) {
                    mma16816(acc[mi * 4 + ni], ah[mi], bh[ni]);
                    mma16816(acc[mi * 4 + ni], ah[mi], bl[ni]);
                    mma16816(acc[mi * 4 + ni], al[mi], bh[ni]);
                }
        }
        __syncthreads();
    }

    const int rbase = warp_m + (lane >> 2);
    const int cbase = warp_n + (lane & 3) * 2;
#pragma unroll
    for (int mi = 0; mi < 4; mi++)
#pragma unroll
        for (int ni = 0; ni < 4; ni++) {
            const float* a4 = acc[mi * 4 + ni];
            int c = cbase + ni * 8;
            float bf0 = bfs[c], bf1 = bfs[c + 1];
            int r0 = bm + rbase + mi * 16;
            float v0 = a4[0] + bf0, v1 = a4[1] + bf1;
            float v2 = a4[2] + bf0, v3 = a4[3] + bf1;
            if (Ch) {
                uint32_t h0, l0, h1, l1;
                split2(v0, v1, h0, l0);
                split2(v2, v3, h1, l1);
                *reinterpret_cast<uint32_t*>(&Ch[(size_t)r0 * H + bn + c]) = h0;
                *reinterpret_cast<uint32_t*>(&Cl[(size_t)r0 * H + bn + c]) = l0;
                *reinterpret_cast<uint32_t*>(&Ch[(size_t)(r0 + 8) * H + bn + c]) = h1;
                *reinterpret_cast<uint32_t*>(&Cl[(size_t)(r0 + 8) * H + bn + c]) = l1;
            } else {
                *(float2*)&Cf[(size_t)r0 * H + bn + c] = make_float2(v0, v1);
                *(float2*)&Cf[(size_t)(r0 + 8) * H + bn + c] = make_float2(v2, v3);
            }
        }
}

// ---------------- Flash attention on mma.sync (bf16 split, 3-pass) ----------------
// Per CTA: (qtile=128, head, batch). 8 warps, each owns 16 q-rows.
// smem: Q resident (hi+lo), K/V double-buffered stages.
#define ALD 144                    // bytes per 64-elem row (128 + 16 pad)
#define ATILE (128 * ALD)          // 18432 bytes, one component
#define AQ_H 0
#define AQ_L ATILE
#define AST_BASE (2 * ATILE)
#define AST_SZ (4 * ATILE)         // kh, kl, vh, vl
#define AK_H 0
#define AK_L ATILE
#define AV_H (2 * ATILE)
#define AV_L (3 * ATILE)
#define ATT_SMEM (2 * ATILE + 2 * AST_SZ)   // 184320 bytes

__global__ __launch_bounds__(256, 1) void attn_tc(
    const __nv_bfloat16* __restrict__ Qh, const __nv_bfloat16* __restrict__ Ql,
    const __nv_bfloat16* __restrict__ Kh, const __nv_bfloat16* __restrict__ Kl,
    const __nv_bfloat16* __restrict__ Vh, const __nv_bfloat16* __restrict__ Vl,
    __nv_bfloat16* __restrict__ Ch, __nv_bfloat16* __restrict__ Cl)
{
    char* smem = (char*)smf;
    const uint32_t sb = smem_u32(smem);
    const int tid = threadIdx.x, wid = tid >> 5, lane = tid & 31;
    const int qt = blockIdx.x, hh = blockIdx.y, b = blockIdx.z;
    const int lane4 = lane & 3, laneR = lane >> 2;

    // global byte offset of (token, head-slice) row start
    const size_t hbyte = (size_t)hh * HD * 2;

    auto load_q = [&]() {
#pragma unroll
        for (int t = 0; t < 4; t++) {
            int i = t * 256 + tid;            // 0..1023
            int r = i >> 3, c = i & 7;
            size_t g = ((size_t)(b * 1024 + qt * 128 + r)) * 2048 + hbyte + c * 16;
            uint32_t off = (uint32_t)(r * ALD + c * 16);
            cp16(sb + AQ_H + off, (const char*)Qh + g);
            cp16(sb + AQ_L + off, (const char*)Ql + g);
        }
    };
    auto load_kv = [&](int kt) {
        uint32_t st = sb + AST_BASE + (uint32_t)(kt & 1) * AST_SZ;
#pragma unroll
        for (int t = 0; t < 4; t++) {
            int i = t * 256 + tid;
            int r = i >> 3, c = i & 7;
            size_t g = ((size_t)(b * 1024 + kt * 128 + r)) * 2048 + hbyte + c * 16;
            uint32_t off = (uint32_t)(r * ALD + c * 16);
            cp16(st + AK_H + off, (const char*)Kh + g);
            cp16(st + AK_L + off, (const char*)Kl + g);
            cp16(st + AV_H + off, (const char*)Vh + g);
            cp16(st + AV_L + off, (const char*)Vl + g);
        }
    };

    load_q();
    load_kv(0);
    CP_COMMIT();

    uint32_t qhf[4][4], qlf[4][4];
    float o_acc[8][4];
#pragma unroll
    for (int i = 0; i < 8; i++)
#pragma unroll
        for (int j = 0; j < 4; j++) o_acc[i][j] = 0.f;
    float m0 = -1.0e30f, m1 = -1.0e30f, l0 = 0.f, l1 = 0.f;

    for (int kt = 0; kt < 8; kt++) {
        if (kt + 1 < 8) {
            load_kv(kt + 1);
            CP_COMMIT();
            CP_WAIT(1);
        } else {
            CP_WAIT(0);
        }
        __syncthreads();

        if (kt == 0) {
            // Q fragments (kept in regs for all ktiles)
            uint32_t qoff = (uint32_t)((wid * 16 + (lane & 15)) * ALD + ((lane >> 4) * 8) * 2);
#pragma unroll
            for (int kc = 0; kc < 4; kc++) {
                ldsm4(qhf[kc], sb + AQ_H + qoff + kc * 32);
                ldsm4(qlf[kc], sb + AQ_L + qoff + kc * 32);
            }
        }

        uint32_t st = sb + AST_BASE + (uint32_t)(kt & 1) * AST_SZ;

        // ---- S = Q K^T (3-pass) ----
        float s_acc[16][4];
#pragma unroll
        for (int j = 0; j < 16; j++)
#pragma unroll
            for (int q = 0; q < 4; q++) s_acc[j][q] = 0.f;

        uint32_t kbase = st + (uint32_t)((lane & 7) * ALD + (((lane >> 3) & 1) * 8) * 2);
#pragma unroll
        for (int j = 0; j < 16; j++) {
            uint32_t krow = kbase + (uint32_t)(j * 8 * ALD);
#pragma unroll
            for (int kc = 0; kc < 4; kc++) {
                uint32_t kh2[2], kl2[2];
                ldsm2(kh2, AK_H + krow + kc * 32);
                ldsm2(kl2, AK_L + krow + kc * 32);
                mma16816(s_acc[j], qhf[kc], kh2);
                mma16816(s_acc[j], qhf[kc], kl2);
                mma16816(s_acc[j], qlf[kc], kh2);
            }
        }

        // ---- online softmax on fragments ----
        float mx0 = -1.0e30f, mx1 = -1.0e30f;
#pragma unroll
        for (int j = 0; j < 16; j++) {
            s_acc[j][0] *= 0.125f; s_acc[j][1] *= 0.125f;
            s_acc[j][2] *= 0.125f; s_acc[j][3] *= 0.125f;
            mx0 = fmaxf(mx0, fmaxf(s_acc[j][0], s_acc[j][1]));
            mx1 = fmaxf(mx1, fmaxf(s_acc[j][2], s_acc[j][3]));
        }
        mx0 = fmaxf(mx0, __shfl_xor_sync(0xffffffffu, mx0, 1));
        mx0 = fmaxf(mx0, __shfl_xor_sync(0xffffffffu, mx0, 2));
        mx1 = fmaxf(mx1, __shfl_xor_sync(0xffffffffu, mx1, 1));
        mx1 = fmaxf(mx1, __shfl_xor_sync(0xffffffffu, mx1, 2));
        float mn0 = fmaxf(m0, mx0), mn1 = fmaxf(m1, mx1);
        float cr0 = __expf(m0 - mn0), cr1 = __expf(m1 - mn1);
        float rs0 = 0.f, rs1 = 0.f;
#pragma unroll
        for (int j = 0; j < 16; j++) {
            float p0 = __expf(s_acc[j][0] - mn0);
            float p1 = __expf(s_acc[j][1] - mn0);
            float p2 = __expf(s_acc[j][2] - mn1);
            float p3 = __expf(s_acc[j][3] - mn1);
            s_acc[j][0] = p0; s_acc[j][1] = p1; s_acc[j][2] = p2; s_acc[j][3] = p3;
            rs0 += p0 + p1; rs1 += p2 + p3;
        }
        rs0 += __shfl_xor_sync(0xffffffffu, rs0, 1);
        rs0 += __shfl_xor_sync(0xffffffffu, rs0, 2);
        rs1 += __shfl_xor_sync(0xffffffffu, rs1, 1);
        rs1 += __shfl_xor_sync(0xffffffffu, rs1, 2);
        l0 = l0 * cr0 + rs0; m0 = mn0;
        l1 = l1 * cr1 + rs1; m1 = mn1;
#pragma unroll
        for (int nt = 0; nt < 8; nt++) {
            o_acc[nt][0] *= cr0; o_acc[nt][1] *= cr0;
            o_acc[nt][2] *= cr1; o_acc[nt][3] *= cr1;
        }

        // ---- O += P V (3-pass; P split in regs) ----
        uint32_t vbase = st + (uint32_t)((lane & 15) * ALD);
#pragma unroll
        for (int kc = 0; kc < 8; kc++) {
            uint32_t ph[4], pl[4];
            split2(s_acc[2 * kc][0], s_acc[2 * kc][1], ph[0], pl[0]);
            split2(s_acc[2 * kc][2], s_acc[2 * kc][3], ph[1], pl[1]);
            split2(s_acc[2 * kc + 1][0], s_acc[2 * kc + 1][1], ph[2], pl[2]);
            split2(s_acc[2 * kc + 1][2], s_acc[2 * kc + 1][3], ph[3], pl[3]);
            uint32_t vrow = vbase + (uint32_t)(kc * 16 * ALD);
#pragma unroll
            for (int nt = 0; nt < 8; nt++) {
                uint32_t vh2[2], vl2[2];
                ldsm2t(vh2, AV_H + vrow + nt * 16);
                ldsm2t(vl2, AV_L + vrow + nt * 16);
                mma16816(o_acc[nt], ph, vh2);
                mma16816(o_acc[nt], ph, vl2);
                mma16816(o_acc[nt], pl, vh2);
            }
        }
        __syncthreads();
    }

    // ---- normalize + write ctx hi/lo bf16 ----
    float inv0 = 1.0f / l0, inv1 = 1.0f / l1;
    size_t row0 = (size_t)(b * 1024 + qt * 128 + wid * 16 + laneR);
    size_t col = (size_t)hh * HD + lane4 * 2;
#pragma unroll
    for (int nt = 0; nt < 8; nt++) {
        float v0 = o_acc[nt][0] * inv0, v1 = o_acc[nt][1] * inv0;
        float v2 = o_acc[nt][2] * inv1, v3 = o_acc[nt][3] * inv1;
        uint32_t h0, l0p, h1, l1p;
        split2(v0, v1, h0, l0p);
        split2(v2, v3, h1, l1p);
        size_t o0 = row0 * H + col + nt * 8;
        size_t o1 = (row0 + 8) * H + col + nt * 8;
        *reinterpret_cast<uint32_t*>(&Ch[o0]) = h0;
        *reinterpret_cast<uint32_t*>(&Cl[o0]) = l0p;
        *reinterpret_cast<uint32_t*>(&Ch[o1]) = h1;
        *reinterpret_cast<uint32_t*>(&Cl[o1]) = l1p;
    }
}

// ---------------- launcher ----------------
extern "C" void kernel_launch(void* const* d_in, const int* in_sizes, int n_in,
                              void* d_out, int out_size)
{
    const float* x = (const float*)d_in[0];
    __nv_bfloat16 *wh, *wl, *xh, *xl, *qkvh, *qkvl, *ch, *cl;
    cudaGetSymbolAddress((void**)&wh, g_wh);
    cudaGetSymbolAddress((void**)&wl, g_wl);
    cudaGetSymbolAddress((void**)&xh, g_xh);
    cudaGetSymbolAddress((void**)&xl, g_xl);
    cudaGetSymbolAddress((void**)&qkvh, g_qkvh);
    cudaGetSymbolAddress((void**)&qkvl, g_qkvl);
    cudaGetSymbolAddress((void**)&ch, g_ch);
    cudaGetSymbolAddress((void**)&cl, g_cl);

    cudaStreamCaptureStatus cst = cudaStreamCaptureStatusNone;
    cudaError_t qerr = cudaStreamIsCapturing((cudaStream_t)0, &cst);
    if (qerr != cudaSuccess || cst != cudaStreamCaptureStatusActive) {
        cudaFuncSetAttribute(gemm_tc,
                             cudaFuncAttributeMaxDynamicSharedMemorySize, GEMM_SMEM);
        cudaFuncSetAttribute(attn_tc,
                             cudaFuncAttributeMaxDynamicSharedMemorySize, ATT_SMEM);
    }

    dim3 rg(4, 64);
    dim3 gg(8, 128);

    for (int p = 0; p < 4; p++) {
        const float* W  = (const float*)d_in[1 + p * 5 + 0];
        const float* LM = (const float*)d_in[1 + p * 5 + 2];
        const float* RM = (const float*)d_in[1 + p * 5 + 3];
        const float* F  = (const float*)d_in[1 + p * 5 + 4];
        recon2_kernel<<<rg, 256>>>(W, LM, RM, F, wh + (size_t)p * HH, wl + (size_t)p * HH);
    }
    split_kernel<<<(NTOK * H) / 1024, 256>>>(x, xh, xl);

    for (int p = 0; p < 3; p++) {
        const float* bias = (const float*)d_in[1 + p * 5 + 1];
        const float* F    = (const float*)d_in[1 + p * 5 + 4];
        gemm_tc<<<gg, 256, GEMM_SMEM>>>(xh, xl, wh + (size_t)p * HH, wl + (size_t)p * HH,
                                        bias, F, nullptr,
                                        qkvh + (size_t)p * NTOK * H,
                                        qkvl + (size_t)p * NTOK * H);
    }
    attn_tc<<<dim3(8, NH, 16), 256, ATT_SMEM>>>(
        qkvh, qkvl,
        qkvh + (size_t)NTOK * H, qkvl + (size_t)NTOK * H,
        qkvh + 2ull * NTOK * H, qkvl + 2ull * NTOK * H,
        ch, cl);
    {
        const float* bias = (const float*)d_in[1 + 3 * 5 + 1];
        const float* F    = (const float*)d_in[1 + 3 * 5 + 4];
        gemm_tc<<<gg, 256, GEMM_SMEM>>>(ch, cl, wh + 3ull * HH, wl + 3ull * HH,
                                        bias, F, (float*)d_out, nullptr, nullptr);
    }
}

// round 13
// speedup vs baseline: 3.0874x; 1.7648x over previous
#include <cuda_runtime.h>
#include <cuda_bf16.h>
#include <cuda_fp16.h>
#include <math.h>
#include <stdint.h>

#define H    1024
#define NTOK 16384   // B*S
#define NH   16
#define HD   64
#define HH   (1024*1024)

// ---------------- scratch (static device globals; no allocation) ----------------
__device__ __nv_bfloat16 g_wh[2ull * HH], g_wl[2ull * HH];   // q,k weights bf16 hi/lo
__device__ __half        g_w16[2ull * HH];                   // v,o weights fp16 single
__device__ __nv_bfloat16 g_xh[(size_t)NTOK * H], g_xl[(size_t)NTOK * H];
__device__ __half        g_xh16[(size_t)NTOK * H], g_xl16[(size_t)NTOK * H];
__device__ __nv_bfloat16 g_qkvh[2ull * NTOK * H], g_qkvl[2ull * NTOK * H]; // q,k
__device__ __half        g_v16[(size_t)NTOK * H];
__device__ __half        g_ch16[(size_t)NTOK * H], g_cl16[(size_t)NTOK * H];

// ---------------- PTX helpers (sm_80-era: valid on plain sm_103 target) ----------------
__device__ __forceinline__ uint32_t smem_u32(const void* p) {
    uint32_t a;
    asm("{ .reg .u64 t; cvta.to.shared.u64 t, %1; cvt.u32.u64 %0, t; }" : "=r"(a) : "l"(p));
    return a;
}
__device__ __forceinline__ void cp16(uint32_t dst, const void* src) {
    asm volatile("cp.async.cg.shared.global [%0], [%1], 16;" :: "r"(dst), "l"(src));
}
#define CP_COMMIT() asm volatile("cp.async.commit_group;" ::: "memory")
#define CP_WAIT(n)  asm volatile("cp.async.wait_group %0;" :: "n"(n) : "memory")

__device__ __forceinline__ void ldsm4(uint32_t* r, uint32_t addr) {
    asm volatile("ldmatrix.sync.aligned.m8n8.x4.shared.b16 {%0,%1,%2,%3}, [%4];"
        : "=r"(r[0]), "=r"(r[1]), "=r"(r[2]), "=r"(r[3]) : "r"(addr));
}
__device__ __forceinline__ void ldsm2(uint32_t* r, uint32_t addr) {
    asm volatile("ldmatrix.sync.aligned.m8n8.x2.shared.b16 {%0,%1}, [%2];"
        : "=r"(r[0]), "=r"(r[1]) : "r"(addr));
}
__device__ __forceinline__ void ldsm2t(uint32_t* r, uint32_t addr) {
    asm volatile("ldmatrix.sync.aligned.m8n8.x2.trans.shared.b16 {%0,%1}, [%2];"
        : "=r"(r[0]), "=r"(r[1]) : "r"(addr));
}
__device__ __forceinline__ void mma_bf(float* d, const uint32_t* a, const uint32_t* b) {
    asm volatile(
        "mma.sync.aligned.m16n8k16.row.col.f32.bf16.bf16.f32 "
        "{%0,%1,%2,%3}, {%4,%5,%6,%7}, {%8,%9}, {%0,%1,%2,%3};"
        : "+f"(d[0]), "+f"(d[1]), "+f"(d[2]), "+f"(d[3])
        : "r"(a[0]), "r"(a[1]), "r"(a[2]), "r"(a[3]), "r"(b[0]), "r"(b[1]));
}
__device__ __forceinline__ void mma_f16(float* d, const uint32_t* a, const uint32_t* b) {
    asm volatile(
        "mma.sync.aligned.m16n8k16.row.col.f32.f16.f16.f32 "
        "{%0,%1,%2,%3}, {%4,%5,%6,%7}, {%8,%9}, {%0,%1,%2,%3};"
        : "+f"(d[0]), "+f"(d[1]), "+f"(d[2]), "+f"(d[3])
        : "r"(a[0]), "r"(a[1]), "r"(a[2]), "r"(a[3]), "r"(b[0]), "r"(b[1]));
}
__device__ __forceinline__ void split2(float v0, float v1, uint32_t& hi, uint32_t& lo) {
    __nv_bfloat162 h = __float22bfloat162_rn(make_float2(v0, v1));
    float2 back = __bfloat1622float2(h);
    __nv_bfloat162 l = __float22bfloat162_rn(make_float2(v0 - back.x, v1 - back.y));
    hi = *reinterpret_cast<uint32_t*>(&h);
    lo = *reinterpret_cast<uint32_t*>(&l);
}
__device__ __forceinline__ void split2h(float v0, float v1, uint32_t& hi, uint32_t& lo) {
    __half2 h = __float22half2_rn(make_float2(v0, v1));
    float2 back = __half22float2(h);
    __half2 l = __float22half2_rn(make_float2(v0 - back.x, v1 - back.y));
    hi = *reinterpret_cast<uint32_t*>(&h);
    lo = *reinterpret_cast<uint32_t*>(&l);
}

// ---------------- recon: w=(LM@RM+W)*F -> bf16 hi/lo (mode 0) or fp16 single (mode 1) ----------------
__global__ __launch_bounds__(256) void recon2_kernel(
    const float* __restrict__ W, const float* __restrict__ LM,
    const float* __restrict__ RM, const float* __restrict__ F,
    __nv_bfloat16* __restrict__ wh, __nv_bfloat16* __restrict__ wl,
    __half* __restrict__ w16, int mode)
{
    __shared__ float lms[16 * 64];
    const int o0 = blockIdx.y * 16;
    const int i  = blockIdx.x * 256 + threadIdx.x;
    for (int t = threadIdx.x; t < 16 * 64; t += 256) lms[t] = LM[o0 * 64 + t];
    __syncthreads();
    float acc[16];
#pragma unroll
    for (int j = 0; j < 16; j++) acc[j] = 0.f;
    for (int k = 0; k < 64; k++) {
        float rm = RM[k * H + i];
#pragma unroll
        for (int j = 0; j < 16; j++) acc[j] = fmaf(lms[j * 64 + k], rm, acc[j]);
    }
#pragma unroll
    for (int j = 0; j < 16; j++) {
        int o = o0 + j;
        float w = (acc[j] + W[(size_t)o * H + i]) * F[o];
        if (mode == 0) {
            __nv_bfloat16 hi = __float2bfloat16(w);
            wh[(size_t)o * H + i] = hi;
            wl[(size_t)o * H + i] = __float2bfloat16(w - __bfloat162float(hi));
        } else {
            w16[(size_t)o * H + i] = __float2half(w);
        }
    }
}

// ---------------- x split: fp32 -> bf16 hi/lo + fp16 hi/lo ----------------
__global__ __launch_bounds__(256) void split_kernel(
    const float* __restrict__ x, __nv_bfloat16* __restrict__ xh,
    __nv_bfloat16* __restrict__ xl, __half* __restrict__ xh16,
    __half* __restrict__ xl16)
{
    size_t i = ((size_t)blockIdx.x * 256 + threadIdx.x) * 4;
    float4 v = *(const float4*)(x + i);
    uint32_t h01, l01, h23, l23;
    split2(v.x, v.y, h01, l01);
    split2(v.z, v.w, h23, l23);
    *reinterpret_cast<uint32_t*>(xh + i)     = h01;
    *reinterpret_cast<uint32_t*>(xh + i + 2) = h23;
    *reinterpret_cast<uint32_t*>(xl + i)     = l01;
    *reinterpret_cast<uint32_t*>(xl + i + 2) = l23;
    split2h(v.x, v.y, h01, l01);
    split2h(v.z, v.w, h23, l23);
    *reinterpret_cast<uint32_t*>(xh16 + i)     = h01;
    *reinterpret_cast<uint32_t*>(xh16 + i + 2) = h23;
    *reinterpret_cast<uint32_t*>(xl16 + i)     = l01;
    *reinterpret_cast<uint32_t*>(xl16 + i + 2) = l23;
}

// ---------------- bf16 3-pass GEMM (q,k): C = A*B^T + bias*F -> bf16 hi/lo ----------------
#define LDE 40
#define TILE_B (128 * LDE * 2)
#define STAGE_B (4 * TILE_B)
#define GEMM_SMEM (2 * STAGE_B + 512)
#define KSTAGES 32

extern __shared__ float smf[];

__global__ __launch_bounds__(256, 1) void gemm_bf(
    const __nv_bfloat16* __restrict__ Ah, const __nv_bfloat16* __restrict__ Al,
    const __nv_bfloat16* __restrict__ Bh, const __nv_bfloat16* __restrict__ Bl,
    const float* __restrict__ bias, const float* __restrict__ F,
    __nv_bfloat16* __restrict__ Ch, __nv_bfloat16* __restrict__ Cl)
{
    char* smem = (char*)smf;
    const uint32_t sb = smem_u32(smem);
    float* bfs = (float*)(smem + 2 * STAGE_B);
    const int tid = threadIdx.x, wid = tid >> 5, lane = tid & 31;
    const int bm = blockIdx.y * 128, bn = blockIdx.x * 128;

    if (tid < 128) bfs[tid] = bias[bn + tid] * F[bn + tid];

    const char* gA_h = (const char*)Ah + (size_t)bm * 2048;
    const char* gA_l = (const char*)Al + (size_t)bm * 2048;
    const char* gB_h = (const char*)Bh + (size_t)bn * 2048;
    const char* gB_l = (const char*)Bl + (size_t)bn * 2048;

    auto load_stage = [&](int s) {
        uint32_t st = sb + (uint32_t)(s & 1) * STAGE_B;
        size_t kb = (size_t)s * 64;
#pragma unroll
        for (int it = 0; it < 2; it++) {
            int i = it * 256 + tid;
            int r = i >> 2, c = i & 3;
            uint32_t off = (uint32_t)(r * (LDE * 2) + c * 16);
            size_t g = (size_t)r * 2048 + kb + c * 16;
            cp16(st + 0 * TILE_B + off, gA_h + g);
            cp16(st + 1 * TILE_B + off, gA_l + g);
            cp16(st + 2 * TILE_B + off, gB_h + g);
            cp16(st + 3 * TILE_B + off, gB_l + g);
        }
    };

    float acc[16][4];
#pragma unroll
    for (int i = 0; i < 16; i++)
#pragma unroll
        for (int j = 0; j < 4; j++) acc[i][j] = 0.f;

    const int warp_m = (wid >> 2) * 64;
    const int warp_n = (wid & 3) * 32;
    const uint32_t a_row = warp_m + (lane & 15);
    const uint32_t a_k8  = (lane >> 4) * 8;
    const uint32_t b_row = warp_n + (lane & 7);
    const uint32_t b_k8  = ((lane >> 3) & 1) * 8;

    load_stage(0);
    CP_COMMIT();

    for (int s = 0; s < KSTAGES; s++) {
        if (s + 1 < KSTAGES) {
            load_stage(s + 1);
            CP_COMMIT();
            CP_WAIT(1);
        } else {
            CP_WAIT(0);
        }
        __syncthreads();

        uint32_t st = sb + (uint32_t)(s & 1) * STAGE_B;
#pragma unroll
        for (int kk = 0; kk < 32; kk += 16) {
            uint32_t ah[4][4], al[4][4], bh[4][2], bl[4][2];
#pragma unroll
            for (int mi = 0; mi < 4; mi++) {
                uint32_t ao = ((a_row + mi * 16) * LDE + kk + a_k8) * 2;
                ldsm4(ah[mi], st + 0 * TILE_B + ao);
                ldsm4(al[mi], st + 1 * TILE_B + ao);
            }
#pragma unroll
            for (int ni = 0; ni < 4; ni++) {
                uint32_t bo = ((b_row + ni * 8) * LDE + kk + b_k8) * 2;
                ldsm2(bh[ni], st + 2 * TILE_B + bo);
                ldsm2(bl[ni], st + 3 * TILE_B + bo);
            }
#pragma unroll
            for (int mi = 0; mi < 4; mi++)
#pragma unroll
                for (int ni = 0; ni < 4; ni++) {
                    mma_bf(acc[mi * 4 + ni], ah[mi], bh[ni]);
                    mma_bf(acc[mi * 4 + ni], ah[mi], bl[ni]);
                    mma_bf(acc[mi * 4 + ni], al[mi], bh[ni]);
                }
        }
        __syncthreads();
    }

    const int rbase = warp_m + (lane >> 2);
    const int cbase = warp_n + (lane & 3) * 2;
#pragma unroll
    for (int mi = 0; mi < 4; mi++)
#pragma unroll
        for (int ni = 0; ni < 4; ni++) {
            const float* a4 = acc[mi * 4 + ni];
            int c = cbase + ni * 8;
            float bf0 = bfs[c], bf1 = bfs[c + 1];
            int r0 = bm + rbase + mi * 16;
            uint32_t h0, l0, h1, l1;
            split2(a4[0] + bf0, a4[1] + bf1, h0, l0);
            split2(a4[2] + bf0, a4[3] + bf1, h1, l1);
            *reinterpret_cast<uint32_t*>(&Ch[(size_t)r0 * H + bn + c]) = h0;
            *reinterpret_cast<uint32_t*>(&Cl[(size_t)r0 * H + bn + c]) = l0;
            *reinterpret_cast<uint32_t*>(&Ch[(size_t)(r0 + 8) * H + bn + c]) = h1;
            *reinterpret_cast<uint32_t*>(&Cl[(size_t)(r0 + 8) * H + bn + c]) = l1;
        }
}

// ---------------- fp16 2-pass GEMM (v,o): C = (Ah+Al)*Bh^T + bias*F ----------------
#define ST16_B (3 * TILE_B)
#define GEMM16_SMEM (2 * ST16_B + 512)

__global__ __launch_bounds__(256, 1) void gemm_16(
    const __half* __restrict__ Ah, const __half* __restrict__ Al,
    const __half* __restrict__ Bh,
    const float* __restrict__ bias, const float* __restrict__ F,
    float* __restrict__ Cf, __half* __restrict__ C16)
{
    char* smem = (char*)smf;
    const uint32_t sb = smem_u32(smem);
    float* bfs = (float*)(smem + 2 * ST16_B);
    const int tid = threadIdx.x, wid = tid >> 5, lane = tid & 31;
    const int bm = blockIdx.y * 128, bn = blockIdx.x * 128;

    if (tid < 128) bfs[tid] = bias[bn + tid] * F[bn + tid];

    const char* gA_h = (const char*)Ah + (size_t)bm * 2048;
    const char* gA_l = (const char*)Al + (size_t)bm * 2048;
    const char* gB_h = (const char*)Bh + (size_t)bn * 2048;

    auto load_stage = [&](int s) {
        uint32_t st = sb + (uint32_t)(s & 1) * ST16_B;
        size_t kb = (size_t)s * 64;
#pragma unroll
        for (int it = 0; it < 2; it++) {
            int i = it * 256 + tid;
            int r = i >> 2, c = i & 3;
            uint32_t off = (uint32_t)(r * (LDE * 2) + c * 16);
            size_t g = (size_t)r * 2048 + kb + c * 16;
            cp16(st + 0 * TILE_B + off, gA_h + g);
            cp16(st + 1 * TILE_B + off, gA_l + g);
            cp16(st + 2 * TILE_B + off, gB_h + g);
        }
    };

    float acc[16][4];
#pragma unroll
    for (int i = 0; i < 16; i++)
#pragma unroll
        for (int j = 0; j < 4; j++) acc[i][j] = 0.f;

    const int warp_m = (wid >> 2) * 64;
    const int warp_n = (wid & 3) * 32;
    const uint32_t a_row = warp_m + (lane & 15);
    const uint32_t a_k8  = (lane >> 4) * 8;
    const uint32_t b_row = warp_n + (lane & 7);
    const uint32_t b_k8  = ((lane >> 3) & 1) * 8;

    load_stage(0);
    CP_COMMIT();

    for (int s = 0; s < KSTAGES; s++) {
        if (s + 1 < KSTAGES) {
            load_stage(s + 1);
            CP_COMMIT();
            CP_WAIT(1);
        } else {
            CP_WAIT(0);
        }
        __syncthreads();

        uint32_t st = sb + (uint32_t)(s & 1) * ST16_B;
#pragma unroll
        for (int kk = 0; kk < 32; kk += 16) {
            uint32_t ah[4][4], al[4][4], bh[4][2];
#pragma unroll
            for (int mi = 0; mi < 4; mi++) {
                uint32_t ao = ((a_row + mi * 16) * LDE + kk + a_k8) * 2;
                ldsm4(ah[mi], st + 0 * TILE_B + ao);
                ldsm4(al[mi], st + 1 * TILE_B + ao);
            }
#pragma unroll
            for (int ni = 0; ni < 4; ni++) {
                uint32_t bo = ((b_row + ni * 8) * LDE + kk + b_k8) * 2;
                ldsm2(bh[ni], st + 2 * TILE_B + bo);
            }
#pragma unroll
            for (int mi = 0; mi < 4; mi++)
#pragma unroll
                for (int ni = 0; ni < 4; ni++) {
                    mma_f16(acc[mi * 4 + ni], ah[mi], bh[ni]);
                    mma_f16(acc[mi * 4 + ni], al[mi], bh[ni]);
                }
        }
        __syncthreads();
    }

    const int rbase = warp_m + (lane >> 2);
    const int cbase = warp_n + (lane & 3) * 2;
#pragma unroll
    for (int mi = 0; mi < 4; mi++)
#pragma unroll
        for (int ni = 0; ni < 4; ni++) {
            const float* a4 = acc[mi * 4 + ni];
            int c = cbase + ni * 8;
            float bf0 = bfs[c], bf1 = bfs[c + 1];
            int r0 = bm + rbase + mi * 16;
            float v0 = a4[0] + bf0, v1 = a4[1] + bf1;
            float v2 = a4[2] + bf0, v3 = a4[3] + bf1;
            if (C16) {
                __half2 p0 = __float22half2_rn(make_float2(v0, v1));
                __half2 p1 = __float22half2_rn(make_float2(v2, v3));
                *reinterpret_cast<__half2*>(&C16[(size_t)r0 * H + bn + c]) = p0;
                *reinterpret_cast<__half2*>(&C16[(size_t)(r0 + 8) * H + bn + c]) = p1;
            } else {
                *(float2*)&Cf[(size_t)r0 * H + bn + c] = make_float2(v0, v1);
                *(float2*)&Cf[(size_t)(r0 + 8) * H + bn + c] = make_float2(v2, v3);
            }
        }
}

// ---------------- Flash attention: S bf16 3-pass, PV fp16 2-pass ----------------
#define ALD 144
#define ATILE (128 * ALD)          // 18432 bytes per component
#define AQ_H 0
#define AQ_L ATILE
#define AST_BASE (2 * ATILE)
#define AST_SZ (3 * ATILE)         // kh, kl, v16
#define AK_H 0
#define AK_L ATILE
#define AV16 (2 * ATILE)
#define ATT_SMEM (2 * ATILE + 2 * AST_SZ)   // 147456

__global__ __launch_bounds__(256, 1) void attn_tc(
    const __nv_bfloat16* __restrict__ Qh, const __nv_bfloat16* __restrict__ Ql,
    const __nv_bfloat16* __restrict__ Kh, const __nv_bfloat16* __restrict__ Kl,
    const __half* __restrict__ V16,
    __half* __restrict__ Ch, __half* __restrict__ Cl)
{
    char* smem = (char*)smf;
    const uint32_t sb = smem_u32(smem);
    const int tid = threadIdx.x, wid = tid >> 5, lane = tid & 31;
    const int qt = blockIdx.x, hh = blockIdx.y, b = blockIdx.z;
    const int lane4 = lane & 3, laneR = lane >> 2;

    const size_t hbyte = (size_t)hh * HD * 2;

    auto load_q = [&]() {
#pragma unroll
        for (int t = 0; t < 4; t++) {
            int i = t * 256 + tid;
            int r = i >> 3, c = i & 7;
            size_t g = ((size_t)(b * 1024 + qt * 128 + r)) * 2048 + hbyte + c * 16;
            uint32_t off = (uint32_t)(r * ALD + c * 16);
            cp16(sb + AQ_H + off, (const char*)Qh + g);
            cp16(sb + AQ_L + off, (const char*)Ql + g);
        }
    };
    auto load_kv = [&](int kt) {
        uint32_t st = sb + AST_BASE + (uint32_t)(kt & 1) * AST_SZ;
#pragma unroll
        for (int t = 0; t < 4; t++) {
            int i = t * 256 + tid;
            int r = i >> 3, c = i & 7;
            size_t g = ((size_t)(b * 1024 + kt * 128 + r)) * 2048 + hbyte + c * 16;
            uint32_t off = (uint32_t)(r * ALD + c * 16);
            cp16(st + AK_H + off, (const char*)Kh + g);
            cp16(st + AK_L + off, (const char*)Kl + g);
            cp16(st + AV16 + off, (const char*)V16 + g);
        }
    };

    load_q();
    load_kv(0);
    CP_COMMIT();

    uint32_t qhf[4][4], qlf[4][4];
    float o_acc[8][4];
#pragma unroll
    for (int i = 0; i < 8; i++)
#pragma unroll
        for (int j = 0; j < 4; j++) o_acc[i][j] = 0.f;
    float m0 = -1.0e30f, m1 = -1.0e30f, l0 = 0.f, l1 = 0.f;

    for (int kt = 0; kt < 8; kt++) {
        if (kt + 1 < 8) {
            load_kv(kt + 1);
            CP_COMMIT();
            CP_WAIT(1);
        } else {
            CP_WAIT(0);
        }
        __syncthreads();

        if (kt == 0) {
            uint32_t qoff = (uint32_t)((wid * 16 + (lane & 15)) * ALD + ((lane >> 4) * 8) * 2);
#pragma unroll
            for (int kc = 0; kc < 4; kc++) {
                ldsm4(qhf[kc], sb + AQ_H + qoff + kc * 32);
                ldsm4(qlf[kc], sb + AQ_L + qoff + kc * 32);
            }
        }

        uint32_t st = sb + AST_BASE + (uint32_t)(kt & 1) * AST_SZ;

        // ---- S = Q K^T (bf16 3-pass) ----
        float s_acc[16][4];
#pragma unroll
        for (int j = 0; j < 16; j++)
#pragma unroll
            for (int q = 0; q < 4; q++) s_acc[j][q] = 0.f;

        uint32_t kbase = st + (uint32_t)((lane & 7) * ALD + (((lane >> 3) & 1) * 8) * 2);
#pragma unroll
        for (int j = 0; j < 16; j++) {
            uint32_t krow = kbase + (uint32_t)(j * 8 * ALD);
#pragma unroll
            for (int kc = 0; kc < 4; kc++) {
                uint32_t kh2[2], kl2[2];
                ldsm2(kh2, AK_H + krow + kc * 32);
                ldsm2(kl2, AK_L + krow + kc * 32);
                mma_bf(s_acc[j], qhf[kc], kh2);
                mma_bf(s_acc[j], qhf[kc], kl2);
                mma_bf(s_acc[j], qlf[kc], kh2);
            }
        }

        // ---- online softmax ----
        float mx0 = -1.0e30f, mx1 = -1.0e30f;
#pragma unroll
        for (int j = 0; j < 16; j++) {
            s_acc[j][0] *= 0.125f; s_acc[j][1] *= 0.125f;
            s_acc[j][2] *= 0.125f; s_acc[j][3] *= 0.125f;
            mx0 = fmaxf(mx0, fmaxf(s_acc[j][0], s_acc[j][1]));
            mx1 = fmaxf(mx1, fmaxf(s_acc[j][2], s_acc[j][3]));
        }
        mx0 = fmaxf(mx0, __shfl_xor_sync(0xffffffffu, mx0, 1));
        mx0 = fmaxf(mx0, __shfl_xor_sync(0xffffffffu, mx0, 2));
        mx1 = fmaxf(mx1, __shfl_xor_sync(0xffffffffu, mx1, 1));
        mx1 = fmaxf(mx1, __shfl_xor_sync(0xffffffffu, mx1, 2));
        float mn0 = fmaxf(m0, mx0), mn1 = fmaxf(m1, mx1);
        float cr0 = __expf(m0 - mn0), cr1 = __expf(m1 - mn1);
        float rs0 = 0.f, rs1 = 0.f;
#pragma unroll
        for (int j = 0; j < 16; j++) {
            float p0 = __expf(s_acc[j][0] - mn0);
            float p1 = __expf(s_acc[j][1] - mn0);
            float p2 = __expf(s_acc[j][2] - mn1);
            float p3 = __expf(s_acc[j][3] - mn1);
            s_acc[j][0] = p0; s_acc[j][1] = p1; s_acc[j][2] = p2; s_acc[j][3] = p3;
            rs0 += p0 + p1; rs1 += p2 + p3;
        }
        rs0 += __shfl_xor_sync(0xffffffffu, rs0, 1);
        rs0 += __shfl_xor_sync(0xffffffffu, rs0, 2);
        rs1 += __shfl_xor_sync(0xffffffffu, rs1, 1);
        rs1 += __shfl_xor_sync(0xffffffffu, rs1, 2);
        l0 = l0 * cr0 + rs0; m0 = mn0;
        l1 = l1 * cr1 + rs1; m1 = mn1;
#pragma unroll
        for (int nt = 0; nt < 8; nt++) {
            o_acc[nt][0] *= cr0; o_acc[nt][1] *= cr0;
            o_acc[nt][2] *= cr1; o_acc[nt][3] *= cr1;
        }

        // ---- O += P V (fp16 2-pass: P split hi/lo, V single) ----
        uint32_t vbase = st + (uint32_t)((lane & 15) * ALD);
#pragma unroll
        for (int kc = 0; kc < 8; kc++) {
            uint32_t ph[4], pl[4];
            split2h(s_acc[2 * kc][0], s_acc[2 * kc][1], ph[0], pl[0]);
            split2h(s_acc[2 * kc][2], s_acc[2 * kc][3], ph[1], pl[1]);
            split2h(s_acc[2 * kc + 1][0], s_acc[2 * kc + 1][1], ph[2], pl[2]);
            split2h(s_acc[2 * kc + 1][2], s_acc[2 * kc + 1][3], ph[3], pl[3]);
            uint32_t vrow = vbase + (uint32_t)(kc * 16 * ALD);
#pragma unroll
            for (int nt = 0; nt < 8; nt++) {
                uint32_t vh2[2];
                ldsm2t(vh2, AV16 + vrow + nt * 16);
                mma_f16(o_acc[nt], ph, vh2);
                mma_f16(o_acc[nt], pl, vh2);
            }
        }
        __syncthreads();
    }

    // ---- normalize + write ctx fp16 hi/lo ----
    float inv0 = 1.0f / l0, inv1 = 1.0f / l1;
    size_t row0 = (size_t)(b * 1024 + qt * 128 + wid * 16 + laneR);
    size_t col = (size_t)hh * HD + lane4 * 2;
#pragma unroll
    for (int nt = 0; nt < 8; nt++) {
        float v0 = o_acc[nt][0] * inv0, v1 = o_acc[nt][1] * inv0;
        float v2 = o_acc[nt][2] * inv1, v3 = o_acc[nt][3] * inv1;
        uint32_t h0, l0p, h1, l1p;
        split2h(v0, v1, h0, l0p);
        split2h(v2, v3, h1, l1p);
        size_t o0 = row0 * H + col + nt * 8;
        size_t o1 = (row0 + 8) * H + col + nt * 8;
        *reinterpret_cast<uint32_t*>(&Ch[o0]) = h0;
        *reinterpret_cast<uint32_t*>(&Cl[o0]) = l0p;
        *reinterpret_cast<uint32_t*>(&Ch[o1]) = h1;
        *reinterpret_cast<uint32_t*>(&Cl[o1]) = l1p;
    }
}

// ---------------- launcher ----------------
extern "C" void kernel_launch(void* const* d_in, const int* in_sizes, int n_in,
                              void* d_out, int out_size)
{
    const float* x = (const float*)d_in[0];
    __nv_bfloat16 *wh, *wl, *xh, *xl, *qkvh, *qkvl;
    __half *w16, *xh16, *xl16, *v16, *ch16, *cl16;
    cudaGetSymbolAddress((void**)&wh, g_wh);
    cudaGetSymbolAddress((void**)&wl, g_wl);
    cudaGetSymbolAddress((void**)&w16, g_w16);
    cudaGetSymbolAddress((void**)&xh, g_xh);
    cudaGetSymbolAddress((void**)&xl, g_xl);
    cudaGetSymbolAddress((void**)&xh16, g_xh16);
    cudaGetSymbolAddress((void**)&xl16, g_xl16);
    cudaGetSymbolAddress((void**)&qkvh, g_qkvh);
    cudaGetSymbolAddress((void**)&qkvl, g_qkvl);
    cudaGetSymbolAddress((void**)&v16, g_v16);
    cudaGetSymbolAddress((void**)&ch16, g_ch16);
    cudaGetSymbolAddress((void**)&cl16, g_cl16);

    cudaStreamCaptureStatus cst = cudaStreamCaptureStatusNone;
    cudaError_t qerr = cudaStreamIsCapturing((cudaStream_t)0, &cst);
    if (qerr != cudaSuccess || cst != cudaStreamCaptureStatusActive) {
        cudaFuncSetAttribute(gemm_bf,
                             cudaFuncAttributeMaxDynamicSharedMemorySize, GEMM_SMEM);
        cudaFuncSetAttribute(gemm_16,
                             cudaFuncAttributeMaxDynamicSharedMemorySize, GEMM16_SMEM);
        cudaFuncSetAttribute(attn_tc,
                             cudaFuncAttributeMaxDynamicSharedMemorySize, ATT_SMEM);
    }

    dim3 rg(4, 64);
    dim3 gg(8, 128);

    // recon: q,k -> bf16 pair (slots 0,1); v,o -> fp16 single (slots 0,1 of w16)
    for (int p = 0; p < 2; p++) {
        recon2_kernel<<<rg, 256>>>(
            (const float*)d_in[1 + p * 5 + 0], (const float*)d_in[1 + p * 5 + 2],
            (const float*)d_in[1 + p * 5 + 3], (const float*)d_in[1 + p * 5 + 4],
            wh + (size_t)p * HH, wl + (size_t)p * HH, nullptr, 0);
    }
    for (int p = 2; p < 4; p++) {
        recon2_kernel<<<rg, 256>>>(
            (const float*)d_in[1 + p * 5 + 0], (const float*)d_in[1 + p * 5 + 2],
            (const float*)d_in[1 + p * 5 + 3], (const float*)d_in[1 + p * 5 + 4],
            nullptr, nullptr, w16 + (size_t)(p - 2) * HH, 1);
    }
    split_kernel<<<(NTOK * H) / 1024, 256>>>(x, xh, xl, xh16, xl16);

    // q,k: bf16 3-pass
    for (int p = 0; p < 2; p++) {
        gemm_bf<<<gg, 256, GEMM_SMEM>>>(
            xh, xl, wh + (size_t)p * HH, wl + (size_t)p * HH,
            (const float*)d_in[1 + p * 5 + 1], (const float*)d_in[1 + p * 5 + 4],
            qkvh + (size_t)p * NTOK * H, qkvl + (size_t)p * NTOK * H);
    }
    // v: fp16 2-pass -> fp16 single
    gemm_16<<<gg, 256, GEMM16_SMEM>>>(
        xh16, xl16, w16,
        (const float*)d_in[1 + 2 * 5 + 1], (const float*)d_in[1 + 2 * 5 + 4],
        nullptr, v16);

    attn_tc<<<dim3(8, NH, 16), 256, ATT_SMEM>>>(
        qkvh, qkvl, qkvh + (size_t)NTOK * H, qkvl + (size_t)NTOK * H,
        v16, ch16, cl16);

    // o: fp16 2-pass -> fp32 out
    gemm_16<<<gg, 256, GEMM16_SMEM>>>(
        ch16, cl16, w16 + (size_t)HH,
        (const float*)d_in[1 + 3 * 5 + 1], (const float*)d_in[1 + 3 * 5 + 4],
        (float*)d_out, nullptr);
}

// round 14
// speedup vs baseline: 3.2004x; 1.0366x over previous
#include <cuda_runtime.h>
#include <cuda_fp16.h>
#include <math.h>
#include <stdint.h>

#define H    1024
#define NTOK 16384   // B*S
#define NH   16
#define HD   64
#define HH   (1024*1024)

// ---------------- scratch (static device globals; no allocation) ----------------
__device__ __half g_w16[4ull * HH];                 // q,k,v,o weights fp16
__device__ __half g_x16[(size_t)NTOK * H];
__device__ __half g_qkv16[3ull * NTOK * H];
__device__ __half g_c16[(size_t)NTOK * H];

// ---------------- PTX helpers (sm_80-era: valid on plain sm_103 target) ----------------
__device__ __forceinline__ uint32_t smem_u32(const void* p) {
    uint32_t a;
    asm("{ .reg .u64 t; cvta.to.shared.u64 t, %1; cvt.u32.u64 %0, t; }" : "=r"(a) : "l"(p));
    return a;
}
__device__ __forceinline__ void cp16(uint32_t dst, const void* src) {
    asm volatile("cp.async.cg.shared.global [%0], [%1], 16;" :: "r"(dst), "l"(src));
}
#define CP_COMMIT() asm volatile("cp.async.commit_group;" ::: "memory")
#define CP_WAIT(n)  asm volatile("cp.async.wait_group %0;" :: "n"(n) : "memory")

__device__ __forceinline__ void ldsm4(uint32_t* r, uint32_t addr) {
    asm volatile("ldmatrix.sync.aligned.m8n8.x4.shared.b16 {%0,%1,%2,%3}, [%4];"
        : "=r"(r[0]), "=r"(r[1]), "=r"(r[2]), "=r"(r[3]) : "r"(addr));
}
__device__ __forceinline__ void ldsm2(uint32_t* r, uint32_t addr) {
    asm volatile("ldmatrix.sync.aligned.m8n8.x2.shared.b16 {%0,%1}, [%2];"
        : "=r"(r[0]), "=r"(r[1]) : "r"(addr));
}
__device__ __forceinline__ void ldsm2t(uint32_t* r, uint32_t addr) {
    asm volatile("ldmatrix.sync.aligned.m8n8.x2.trans.shared.b16 {%0,%1}, [%2];"
        : "=r"(r[0]), "=r"(r[1]) : "r"(addr));
}
__device__ __forceinline__ void mma_f16(float* d, const uint32_t* a, const uint32_t* b) {
    asm volatile(
        "mma.sync.aligned.m16n8k16.row.col.f32.f16.f16.f32 "
        "{%0,%1,%2,%3}, {%4,%5,%6,%7}, {%8,%9}, {%0,%1,%2,%3};"
        : "+f"(d[0]), "+f"(d[1]), "+f"(d[2]), "+f"(d[3])
        : "r"(a[0]), "r"(a[1]), "r"(a[2]), "r"(a[3]), "r"(b[0]), "r"(b[1]));
}
__device__ __forceinline__ uint32_t pack_h2(float v0, float v1) {
    __half2 h = __float22half2_rn(make_float2(v0, v1));
    return *reinterpret_cast<uint32_t*>(&h);
}

// ---------------- recon: w=(LM@RM+W)*F -> fp16 ----------------
__global__ __launch_bounds__(256) void recon16_kernel(
    const float* __restrict__ W, const float* __restrict__ LM,
    const float* __restrict__ RM, const float* __restrict__ F,
    __half* __restrict__ w16)
{
    __shared__ float lms[16 * 64];
    const int o0 = blockIdx.y * 16;
    const int i  = blockIdx.x * 256 + threadIdx.x;
    for (int t = threadIdx.x; t < 16 * 64; t += 256) lms[t] = LM[o0 * 64 + t];
    __syncthreads();
    float acc[16];
#pragma unroll
    for (int j = 0; j < 16; j++) acc[j] = 0.f;
    for (int k = 0; k < 64; k++) {
        float rm = RM[k * H + i];
#pragma unroll
        for (int j = 0; j < 16; j++) acc[j] = fmaf(lms[j * 64 + k], rm, acc[j]);
    }
#pragma unroll
    for (int j = 0; j < 16; j++) {
        int o = o0 + j;
        w16[(size_t)o * H + i] = __float2half((acc[j] + W[(size_t)o * H + i]) * F[o]);
    }
}

// ---------------- x convert: fp32 -> fp16 ----------------
__global__ __launch_bounds__(256) void cvt16_kernel(
    const float* __restrict__ x, __half* __restrict__ x16)
{
    size_t i = ((size_t)blockIdx.x * 256 + threadIdx.x) * 4;
    float4 v = *(const float4*)(x + i);
    *reinterpret_cast<uint32_t*>(x16 + i)     = pack_h2(v.x, v.y);
    *reinterpret_cast<uint32_t*>(x16 + i + 2) = pack_h2(v.z, v.w);
}

// ---------------- fp16 1-pass GEMM: C[n,o] = sum_i A[n,i]*B[o,i] + bias*F ----------------
#define LDE 40
#define TILE_B (128 * LDE * 2)     // 10240 bytes
#define ST1_B (2 * TILE_B)         // A, B
#define GEMM_SMEM (2 * ST1_B + 512)
#define KSTAGES 32

extern __shared__ float smf[];

__global__ __launch_bounds__(256, 1) void gemm_f16(
    const __half* __restrict__ A16, const __half* __restrict__ B16,
    const float* __restrict__ bias, const float* __restrict__ F,
    float* __restrict__ Cf, __half* __restrict__ C16)
{
    char* smem = (char*)smf;
    const uint32_t sb = smem_u32(smem);
    float* bfs = (float*)(smem + 2 * ST1_B);
    const int tid = threadIdx.x, wid = tid >> 5, lane = tid & 31;
    const int bm = blockIdx.y * 128, bn = blockIdx.x * 128;

    if (tid < 128) bfs[tid] = bias[bn + tid] * F[bn + tid];

    const char* gA = (const char*)A16 + (size_t)bm * 2048;
    const char* gB = (const char*)B16 + (size_t)bn * 2048;

    auto load_stage = [&](int s) {
        uint32_t st = sb + (uint32_t)(s & 1) * ST1_B;
        size_t kb = (size_t)s * 64;
#pragma unroll
        for (int it = 0; it < 2; it++) {
            int i = it * 256 + tid;
            int r = i >> 2, c = i & 3;
            uint32_t off = (uint32_t)(r * (LDE * 2) + c * 16);
            size_t g = (size_t)r * 2048 + kb + c * 16;
            cp16(st + 0 * TILE_B + off, gA + g);
            cp16(st + 1 * TILE_B + off, gB + g);
        }
    };

    float acc[16][4];
#pragma unroll
    for (int i = 0; i < 16; i++)
#pragma unroll
        for (int j = 0; j < 4; j++) acc[i][j] = 0.f;

    const int warp_m = (wid >> 2) * 64;
    const int warp_n = (wid & 3) * 32;
    const uint32_t a_row = warp_m + (lane & 15);
    const uint32_t a_k8  = (lane >> 4) * 8;
    const uint32_t b_row = warp_n + (lane & 7);
    const uint32_t b_k8  = ((lane >> 3) & 1) * 8;

    load_stage(0);
    CP_COMMIT();

    for (int s = 0; s < KSTAGES; s++) {
        if (s + 1 < KSTAGES) {
            load_stage(s + 1);
            CP_COMMIT();
            CP_WAIT(1);
        } else {
            CP_WAIT(0);
        }
        __syncthreads();

        uint32_t st = sb + (uint32_t)(s & 1) * ST1_B;
#pragma unroll
        for (int kk = 0; kk < 32; kk += 16) {
            uint32_t ah[4][4], bh[4][2];
#pragma unroll
            for (int mi = 0; mi < 4; mi++) {
                uint32_t ao = ((a_row + mi * 16) * LDE + kk + a_k8) * 2;
                ldsm4(ah[mi], st + 0 * TILE_B + ao);
            }
#pragma unroll
            for (int ni = 0; ni < 4; ni++) {
                uint32_t bo = ((b_row + ni * 8) * LDE + kk + b_k8) * 2;
                ldsm2(bh[ni], st + 1 * TILE_B + bo);
            }
#pragma unroll
            for (int mi = 0; mi < 4; mi++)
#pragma unroll
                for (int ni = 0; ni < 4; ni++)
                    mma_f16(acc[mi * 4 + ni], ah[mi], bh[ni]);
        }
        __syncthreads();
    }

    const int rbase = warp_m + (lane >> 2);
    const int cbase = warp_n + (lane & 3) * 2;
#pragma unroll
    for (int mi = 0; mi < 4; mi++)
#pragma unroll
        for (int ni = 0; ni < 4; ni++) {
            const float* a4 = acc[mi * 4 + ni];
            int c = cbase + ni * 8;
            float bf0 = bfs[c], bf1 = bfs[c + 1];
            int r0 = bm + rbase + mi * 16;
            float v0 = a4[0] + bf0, v1 = a4[1] + bf1;
            float v2 = a4[2] + bf0, v3 = a4[3] + bf1;
            if (C16) {
                *reinterpret_cast<uint32_t*>(&C16[(size_t)r0 * H + bn + c]) = pack_h2(v0, v1);
                *reinterpret_cast<uint32_t*>(&C16[(size_t)(r0 + 8) * H + bn + c]) = pack_h2(v2, v3);
            } else {
                *(float2*)&Cf[(size_t)r0 * H + bn + c] = make_float2(v0, v1);
                *(float2*)&Cf[(size_t)(r0 + 8) * H + bn + c] = make_float2(v2, v3);
            }
        }
}

// ---------------- Flash attention: all fp16 single, 1-pass S and PV ----------------
#define ALD 144
#define ATILE (128 * ALD)            // 18432 bytes per tile
#define AQ 0
#define AST_BASE ATILE
#define AST_SZ (2 * ATILE)           // k16, v16
#define AK 0
#define AV ATILE
#define ATT_SMEM (ATILE + 2 * AST_SZ)   // 92160

__global__ __launch_bounds__(256, 1) void attn_tc(
    const __half* __restrict__ Q16, const __half* __restrict__ K16,
    const __half* __restrict__ V16, __half* __restrict__ C16)
{
    char* smem = (char*)smf;
    const uint32_t sb = smem_u32(smem);
    const int tid = threadIdx.x, wid = tid >> 5, lane = tid & 31;
    const int qt = blockIdx.x, hh = blockIdx.y, b = blockIdx.z;
    const int lane4 = lane & 3, laneR = lane >> 2;

    const size_t hbyte = (size_t)hh * HD * 2;

    auto load_q = [&]() {
#pragma unroll
        for (int t = 0; t < 4; t++) {
            int i = t * 256 + tid;
            int r = i >> 3, c = i & 7;
            size_t g = ((size_t)(b * 1024 + qt * 128 + r)) * 2048 + hbyte + c * 16;
            cp16(sb + AQ + (uint32_t)(r * ALD + c * 16), (const char*)Q16 + g);
        }
    };
    auto load_kv = [&](int kt) {
        uint32_t st = sb + AST_BASE + (uint32_t)(kt & 1) * AST_SZ;
#pragma unroll
        for (int t = 0; t < 4; t++) {
            int i = t * 256 + tid;
            int r = i >> 3, c = i & 7;
            size_t g = ((size_t)(b * 1024 + kt * 128 + r)) * 2048 + hbyte + c * 16;
            uint32_t off = (uint32_t)(r * ALD + c * 16);
            cp16(st + AK + off, (const char*)K16 + g);
            cp16(st + AV + off, (const char*)V16 + g);
        }
    };

    load_q();
    load_kv(0);
    CP_COMMIT();

    uint32_t qf[4][4];
    float o_acc[8][4];
#pragma unroll
    for (int i = 0; i < 8; i++)
#pragma unroll
        for (int j = 0; j < 4; j++) o_acc[i][j] = 0.f;
    float m0 = -1.0e30f, m1 = -1.0e30f, l0 = 0.f, l1 = 0.f;

    for (int kt = 0; kt < 8; kt++) {
        if (kt + 1 < 8) {
            load_kv(kt + 1);
            CP_COMMIT();
            CP_WAIT(1);
        } else {
            CP_WAIT(0);
        }
        __syncthreads();

        if (kt == 0) {
            uint32_t qoff = (uint32_t)((wid * 16 + (lane & 15)) * ALD + ((lane >> 4) * 8) * 2);
#pragma unroll
            for (int kc = 0; kc < 4; kc++)
                ldsm4(qf[kc], sb + AQ + qoff + kc * 32);
        }

        uint32_t st = sb + AST_BASE + (uint32_t)(kt & 1) * AST_SZ;

        // ---- S = Q K^T (fp16 1-pass) ----
        float s_acc[16][4];
#pragma unroll
        for (int j = 0; j < 16; j++)
#pragma unroll
            for (int q = 0; q < 4; q++) s_acc[j][q] = 0.f;

        uint32_t kbase = st + (uint32_t)((lane & 7) * ALD + (((lane >> 3) & 1) * 8) * 2);
#pragma unroll
        for (int j = 0; j < 16; j++) {
            uint32_t krow = kbase + (uint32_t)(j * 8 * ALD);
#pragma unroll
            for (int kc = 0; kc < 4; kc++) {
                uint32_t k2[2];
                ldsm2(k2, AK + krow + kc * 32);
                mma_f16(s_acc[j], qf[kc], k2);
            }
        }

        // ---- online softmax ----
        float mx0 = -1.0e30f, mx1 = -1.0e30f;
#pragma unroll
        for (int j = 0; j < 16; j++) {
            s_acc[j][0] *= 0.125f; s_acc[j][1] *= 0.125f;
            s_acc[j][2] *= 0.125f; s_acc[j][3] *= 0.125f;
            mx0 = fmaxf(mx0, fmaxf(s_acc[j][0], s_acc[j][1]));
            mx1 = fmaxf(mx1, fmaxf(s_acc[j][2], s_acc[j][3]));
        }
        mx0 = fmaxf(mx0, __shfl_xor_sync(0xffffffffu, mx0, 1));
        mx0 = fmaxf(mx0, __shfl_xor_sync(0xffffffffu, mx0, 2));
        mx1 = fmaxf(mx1, __shfl_xor_sync(0xffffffffu, mx1, 1));
        mx1 = fmaxf(mx1, __shfl_xor_sync(0xffffffffu, mx1, 2));
        float mn0 = fmaxf(m0, mx0), mn1 = fmaxf(m1, mx1);
        float cr0 = __expf(m0 - mn0), cr1 = __expf(m1 - mn1);
        float rs0 = 0.f, rs1 = 0.f;
#pragma unroll
        for (int j = 0; j < 16; j++) {
            float p0 = __expf(s_acc[j][0] - mn0);
            float p1 = __expf(s_acc[j][1] - mn0);
            float p2 = __expf(s_acc[j][2] - mn1);
            float p3 = __expf(s_acc[j][3] - mn1);
            s_acc[j][0] = p0; s_acc[j][1] = p1; s_acc[j][2] = p2; s_acc[j][3] = p3;
            rs0 += p0 + p1; rs1 += p2 + p3;
        }
        rs0 += __shfl_xor_sync(0xffffffffu, rs0, 1);
        rs0 += __shfl_xor_sync(0xffffffffu, rs0, 2);
        rs1 += __shfl_xor_sync(0xffffffffu, rs1, 1);
        rs1 += __shfl_xor_sync(0xffffffffu, rs1, 2);
        l0 = l0 * cr0 + rs0; m0 = mn0;
        l1 = l1 * cr1 + rs1; m1 = mn1;
#pragma unroll
        for (int nt = 0; nt < 8; nt++) {
            o_acc[nt][0] *= cr0; o_acc[nt][1] *= cr0;
            o_acc[nt][2] *= cr1; o_acc[nt][3] *= cr1;
        }

        // ---- O += P V (fp16 1-pass) ----
        uint32_t vbase = st + (uint32_t)((lane & 15) * ALD);
#pragma unroll
        for (int kc = 0; kc < 8; kc++) {
            uint32_t ph[4];
            ph[0] = pack_h2(s_acc[2 * kc][0], s_acc[2 * kc][1]);
            ph[1] = pack_h2(s_acc[2 * kc][2], s_acc[2 * kc][3]);
            ph[2] = pack_h2(s_acc[2 * kc + 1][0], s_acc[2 * kc + 1][1]);
            ph[3] = pack_h2(s_acc[2 * kc + 1][2], s_acc[2 * kc + 1][3]);
            uint32_t vrow = vbase + (uint32_t)(kc * 16 * ALD);
#pragma unroll
            for (int nt = 0; nt < 8; nt++) {
                uint32_t v2[2];
                ldsm2t(v2, AV + vrow + nt * 16);
                mma_f16(o_acc[nt], ph, v2);
            }
        }
        __syncthreads();
    }

    // ---- normalize + write ctx fp16 ----
    float inv0 = 1.0f / l0, inv1 = 1.0f / l1;
    size_t row0 = (size_t)(b * 1024 + qt * 128 + wid * 16 + laneR);
    size_t col = (size_t)hh * HD + lane4 * 2;
#pragma unroll
    for (int nt = 0; nt < 8; nt++) {
        size_t o0 = row0 * H + col + nt * 8;
        size_t o1 = (row0 + 8) * H + col + nt * 8;
        *reinterpret_cast<uint32_t*>(&C16[o0]) =
            pack_h2(o_acc[nt][0] * inv0, o_acc[nt][1] * inv0);
        *reinterpret_cast<uint32_t*>(&C16[o1]) =
            pack_h2(o_acc[nt][2] * inv1, o_acc[nt][3] * inv1);
    }
}

// ---------------- launcher ----------------
extern "C" void kernel_launch(void* const* d_in, const int* in_sizes, int n_in,
                              void* d_out, int out_size)
{
    const float* x = (const float*)d_in[0];
    __half *w16, *x16, *qkv16, *c16;
    cudaGetSymbolAddress((void**)&w16, g_w16);
    cudaGetSymbolAddress((void**)&x16, g_x16);
    cudaGetSymbolAddress((void**)&qkv16, g_qkv16);
    cudaGetSymbolAddress((void**)&c16, g_c16);

    cudaStreamCaptureStatus cst = cudaStreamCaptureStatusNone;
    cudaError_t qerr = cudaStreamIsCapturing((cudaStream_t)0, &cst);
    if (qerr != cudaSuccess || cst != cudaStreamCaptureStatusActive) {
        cudaFuncSetAttribute(gemm_f16,
                             cudaFuncAttributeMaxDynamicSharedMemorySize, GEMM_SMEM);
        cudaFuncSetAttribute(attn_tc,
                             cudaFuncAttributeMaxDynamicSharedMemorySize, ATT_SMEM);
    }

    dim3 rg(4, 64);
    dim3 gg(8, 128);

    for (int p = 0; p < 4; p++) {
        recon16_kernel<<<rg, 256>>>(
            (const float*)d_in[1 + p * 5 + 0], (const float*)d_in[1 + p * 5 + 2],
            (const float*)d_in[1 + p * 5 + 3], (const float*)d_in[1 + p * 5 + 4],
            w16 + (size_t)p * HH);
    }
    cvt16_kernel<<<(NTOK * H) / 1024, 256>>>(x, x16);

    // q, k, v projections -> fp16
    for (int p = 0; p < 3; p++) {
        gemm_f16<<<gg, 256, GEMM_SMEM>>>(
            x16, w16 + (size_t)p * HH,
            (const float*)d_in[1 + p * 5 + 1], (const float*)d_in[1 + p * 5 + 4],
            nullptr, qkv16 + (size_t)p * NTOK * H);
    }

    attn_tc<<<dim3(8, NH, 16), 256, ATT_SMEM>>>(
        qkv16, qkv16 + (size_t)NTOK * H, qkv16 + 2ull * NTOK * H, c16);

    // o projection -> fp32 out
    gemm_f16<<<gg, 256, GEMM_SMEM>>>(
        c16, w16 + 3ull * HH,
        (const float*)d_in[1 + 3 * 5 + 1], (const float*)d_in[1 + 3 * 5 + 4],
        (float*)d_out, nullptr);
}

// round 15
// speedup vs baseline: 3.7403x; 1.1687x over previous
#include <cuda_runtime.h>
#include <cuda_bf16.h>
#include <cuda_fp16.h>
#include <math.h>
#include <stdint.h>

#define H    1024
#define NTOK 16384   // B*S
#define NH   16
#define HD   64
#define HH   (1024*1024)

// ---------------- scratch (static device globals; no allocation) ----------------
__device__ __nv_bfloat16 g_wh[2ull * HH], g_wl[2ull * HH];   // q,k weights bf16 hi/lo
__device__ __half        g_w16[2ull * HH];                   // v,o weights fp16
__device__ __nv_bfloat16 g_xh[(size_t)NTOK * H], g_xl[(size_t)NTOK * H];
__device__ __half        g_x16[(size_t)NTOK * H];
__device__ __nv_bfloat16 g_qkh[2ull * NTOK * H], g_qkl[2ull * NTOK * H]; // q,k pairs
__device__ __half        g_v16[(size_t)NTOK * H];
__device__ __half        g_c16[(size_t)NTOK * H];

// ---------------- PTX helpers (sm_80-era: valid on plain sm_103 target) ----------------
__device__ __forceinline__ uint32_t smem_u32(const void* p) {
    uint32_t a;
    asm("{ .reg .u64 t; cvta.to.shared.u64 t, %1; cvt.u32.u64 %0, t; }" : "=r"(a) : "l"(p));
    return a;
}
__device__ __forceinline__ void cp16(uint32_t dst, const void* src) {
    asm volatile("cp.async.cg.shared.global [%0], [%1], 16;" :: "r"(dst), "l"(src));
}
#define CP_COMMIT() asm volatile("cp.async.commit_group;" ::: "memory")
#define CP_WAIT(n)  asm volatile("cp.async.wait_group %0;" :: "n"(n) : "memory")

__device__ __forceinline__ void ldsm4(uint32_t* r, uint32_t addr) {
    asm volatile("ldmatrix.sync.aligned.m8n8.x4.shared.b16 {%0,%1,%2,%3}, [%4];"
        : "=r"(r[0]), "=r"(r[1]), "=r"(r[2]), "=r"(r[3]) : "r"(addr));
}
__device__ __forceinline__ void ldsm2(uint32_t* r, uint32_t addr) {
    asm volatile("ldmatrix.sync.aligned.m8n8.x2.shared.b16 {%0,%1}, [%2];"
        : "=r"(r[0]), "=r"(r[1]) : "r"(addr));
}
__device__ __forceinline__ void ldsm2t(uint32_t* r, uint32_t addr) {
    asm volatile("ldmatrix.sync.aligned.m8n8.x2.trans.shared.b16 {%0,%1}, [%2];"
        : "=r"(r[0]), "=r"(r[1]) : "r"(addr));
}
__device__ __forceinline__ void mma_bf(float* d, const uint32_t* a, const uint32_t* b) {
    asm volatile(
        "mma.sync.aligned.m16n8k16.row.col.f32.bf16.bf16.f32 "
        "{%0,%1,%2,%3}, {%4,%5,%6,%7}, {%8,%9}, {%0,%1,%2,%3};"
        : "+f"(d[0]), "+f"(d[1]), "+f"(d[2]), "+f"(d[3])
        : "r"(a[0]), "r"(a[1]), "r"(a[2]), "r"(a[3]), "r"(b[0]), "r"(b[1]));
}
__device__ __forceinline__ void mma_f16(float* d, const uint32_t* a, const uint32_t* b) {
    asm volatile(
        "mma.sync.aligned.m16n8k16.row.col.f32.f16.f16.f32 "
        "{%0,%1,%2,%3}, {%4,%5,%6,%7}, {%8,%9}, {%0,%1,%2,%3};"
        : "+f"(d[0]), "+f"(d[1]), "+f"(d[2]), "+f"(d[3])
        : "r"(a[0]), "r"(a[1]), "r"(a[2]), "r"(a[3]), "r"(b[0]), "r"(b[1]));
}
__device__ __forceinline__ void split2(float v0, float v1, uint32_t& hi, uint32_t& lo) {
    __nv_bfloat162 h = __float22bfloat162_rn(make_float2(v0, v1));
    float2 back = __bfloat1622float2(h);
    __nv_bfloat162 l = __float22bfloat162_rn(make_float2(v0 - back.x, v1 - back.y));
    hi = *reinterpret_cast<uint32_t*>(&h);
    lo = *reinterpret_cast<uint32_t*>(&l);
}
__device__ __forceinline__ uint32_t pack_h2(float v0, float v1) {
    __half2 h = __float22half2_rn(make_float2(v0, v1));
    return *reinterpret_cast<uint32_t*>(&h);
}

// ---------------- fused recon: 4 projections in one launch (grid.z = proj) ----------------
struct ReconArgs {
    const float* W[4]; const float* LM[4]; const float* RM[4]; const float* F[4];
    __nv_bfloat16* wh[2]; __nv_bfloat16* wl[2]; __half* w16[2];
};

__global__ __launch_bounds__(256) void recon_all(ReconArgs a)
{
    __shared__ float lms[16 * 64];
    const int p  = blockIdx.z;
    const int o0 = blockIdx.y * 16;
    const int i  = blockIdx.x * 256 + threadIdx.x;
    const float* LM = a.LM[p];
    const float* W  = a.W[p];
    const float* RM = a.RM[p];
    const float* F  = a.F[p];
    for (int t = threadIdx.x; t < 16 * 64; t += 256) lms[t] = LM[o0 * 64 + t];
    __syncthreads();
    float acc[16];
#pragma unroll
    for (int j = 0; j < 16; j++) acc[j] = 0.f;
    for (int k = 0; k < 64; k++) {
        float rm = RM[k * H + i];
#pragma unroll
        for (int j = 0; j < 16; j++) acc[j] = fmaf(lms[j * 64 + k], rm, acc[j]);
    }
#pragma unroll
    for (int j = 0; j < 16; j++) {
        int o = o0 + j;
        float w = (acc[j] + W[(size_t)o * H + i]) * F[o];
        if (p < 2) {
            __nv_bfloat16 hi = __float2bfloat16(w);
            a.wh[p][(size_t)o * H + i] = hi;
            a.wl[p][(size_t)o * H + i] = __float2bfloat16(w - __bfloat162float(hi));
        } else {
            a.w16[p - 2][(size_t)o * H + i] = __float2half(w);
        }
    }
}

// ---------------- x split: fp32 -> bf16 hi/lo + fp16 single ----------------
__global__ __launch_bounds__(256) void split_kernel(
    const float* __restrict__ x, __nv_bfloat16* __restrict__ xh,
    __nv_bfloat16* __restrict__ xl, __half* __restrict__ x16)
{
    size_t i = ((size_t)blockIdx.x * 256 + threadIdx.x) * 4;
    float4 v = *(const float4*)(x + i);
    uint32_t h01, l01, h23, l23;
    split2(v.x, v.y, h01, l01);
    split2(v.z, v.w, h23, l23);
    *reinterpret_cast<uint32_t*>(xh + i)     = h01;
    *reinterpret_cast<uint32_t*>(xh + i + 2) = h23;
    *reinterpret_cast<uint32_t*>(xl + i)     = l01;
    *reinterpret_cast<uint32_t*>(xl + i + 2) = l23;
    *reinterpret_cast<uint32_t*>(x16 + i)     = pack_h2(v.x, v.y);
    *reinterpret_cast<uint32_t*>(x16 + i + 2) = pack_h2(v.z, v.w);
}

// ---------------- bf16 3-pass GEMM (q,k): BK=32, out bf16 hi/lo ----------------
#define LDE 40
#define TILE_B (128 * LDE * 2)     // 10240
#define STAGE_B (4 * TILE_B)       // Ah, Al, Bh, Bl
#define GEMM_SMEM (2 * STAGE_B + 512)
#define KSTAGES 32

extern __shared__ float smf[];

__global__ __launch_bounds__(256, 1) void gemm_bf(
    const __nv_bfloat16* __restrict__ Ah, const __nv_bfloat16* __restrict__ Al,
    const __nv_bfloat16* __restrict__ Bh, const __nv_bfloat16* __restrict__ Bl,
    const float* __restrict__ bias, const float* __restrict__ F,
    __nv_bfloat16* __restrict__ Ch, __nv_bfloat16* __restrict__ Cl)
{
    char* smem = (char*)smf;
    const uint32_t sb = smem_u32(smem);
    float* bfs = (float*)(smem + 2 * STAGE_B);
    const int tid = threadIdx.x, wid = tid >> 5, lane = tid & 31;
    const int bm = blockIdx.y * 128, bn = blockIdx.x * 128;

    if (tid < 128) bfs[tid] = bias[bn + tid] * F[bn + tid];

    const char* gA_h = (const char*)Ah + (size_t)bm * 2048;
    const char* gA_l = (const char*)Al + (size_t)bm * 2048;
    const char* gB_h = (const char*)Bh + (size_t)bn * 2048;
    const char* gB_l = (const char*)Bl + (size_t)bn * 2048;

    auto load_stage = [&](int s) {
        uint32_t st = sb + (uint32_t)(s & 1) * STAGE_B;
        size_t kb = (size_t)s * 64;
#pragma unroll
        for (int it = 0; it < 2; it++) {
            int i = it * 256 + tid;
            int r = i >> 2, c = i & 3;
            uint32_t off = (uint32_t)(r * (LDE * 2) + c * 16);
            size_t g = (size_t)r * 2048 + kb + c * 16;
            cp16(st + 0 * TILE_B + off, gA_h + g);
            cp16(st + 1 * TILE_B + off, gA_l + g);
            cp16(st + 2 * TILE_B + off, gB_h + g);
            cp16(st + 3 * TILE_B + off, gB_l + g);
        }
    };

    float acc[16][4];
#pragma unroll
    for (int i = 0; i < 16; i++)
#pragma unroll
        for (int j = 0; j < 4; j++) acc[i][j] = 0.f;

    const int warp_m = (wid >> 2) * 64;
    const int warp_n = (wid & 3) * 32;
    const uint32_t a_row = warp_m + (lane & 15);
    const uint32_t a_k8  = (lane >> 4) * 8;
    const uint32_t b_row = warp_n + (lane & 7);
    const uint32_t b_k8  = ((lane >> 3) & 1) * 8;

    load_stage(0);
    CP_COMMIT();

    for (int s = 0; s < KSTAGES; s++) {
        if (s + 1 < KSTAGES) {
            load_stage(s + 1);
            CP_COMMIT();
            CP_WAIT(1);
        } else {
            CP_WAIT(0);
        }
        __syncthreads();

        uint32_t st = sb + (uint32_t)(s & 1) * STAGE_B;
#pragma unroll
        for (int kk = 0; kk < 32; kk += 16) {
            uint32_t ah[4][4], al[4][4], bh[4][2], bl[4][2];
#pragma unroll
            for (int mi = 0; mi < 4; mi++) {
                uint32_t ao = ((a_row + mi * 16) * LDE + kk + a_k8) * 2;
                ldsm4(ah[mi], st + 0 * TILE_B + ao);
                ldsm4(al[mi], st + 1 * TILE_B + ao);
            }
#pragma unroll
            for (int ni = 0; ni < 4; ni++) {
                uint32_t bo = ((b_row + ni * 8) * LDE + kk + b_k8) * 2;
                ldsm2(bh[ni], st + 2 * TILE_B + bo);
                ldsm2(bl[ni], st + 3 * TILE_B + bo);
            }
#pragma unroll
            for (int mi = 0; mi < 4; mi++)
#pragma unroll
                for (int ni = 0; ni < 4; ni++) {
                    mma_bf(acc[mi * 4 + ni], ah[mi], bh[ni]);
                    mma_bf(acc[mi * 4 + ni], ah[mi], bl[ni]);
                    mma_bf(acc[mi * 4 + ni], al[mi], bh[ni]);
                }
        }
        __syncthreads();
    }

    const int rbase = warp_m + (lane >> 2);
    const int cbase = warp_n + (lane & 3) * 2;
#pragma unroll
    for (int mi = 0; mi < 4; mi++)
#pragma unroll
        for (int ni = 0; ni < 4; ni++) {
            const float* a4 = acc[mi * 4 + ni];
            int c = cbase + ni * 8;
            float bf0 = bfs[c], bf1 = bfs[c + 1];
            int r0 = bm + rbase + mi * 16;
            uint32_t h0, l0, h1, l1;
            split2(a4[0] + bf0, a4[1] + bf1, h0, l0);
            split2(a4[2] + bf0, a4[3] + bf1, h1, l1);
            *reinterpret_cast<uint32_t*>(&Ch[(size_t)r0 * H + bn + c]) = h0;
            *reinterpret_cast<uint32_t*>(&Cl[(size_t)r0 * H + bn + c]) = l0;
            *reinterpret_cast<uint32_t*>(&Ch[(size_t)(r0 + 8) * H + bn + c]) = h1;
            *reinterpret_cast<uint32_t*>(&Cl[(size_t)(r0 + 8) * H + bn + c]) = l1;
        }
}

// ---------------- fp16 1-pass GEMM (v,o): BK=64, 16 stages ----------------
#define LDE2 72
#define TILE2_B (128 * LDE2 * 2)   // 18432
#define ST2_B (2 * TILE2_B)        // A, B = 36864
#define GEMM16_SMEM (2 * ST2_B + 512)
#define KST2 16

__global__ __launch_bounds__(256, 1) void gemm_f16(
    const __half* __restrict__ A16, const __half* __restrict__ B16,
    const float* __restrict__ bias, const float* __restrict__ F,
    float* __restrict__ Cf, __half* __restrict__ C16)
{
    char* smem = (char*)smf;
    const uint32_t sb = smem_u32(smem);
    float* bfs = (float*)(smem + 2 * ST2_B);
    const int tid = threadIdx.x, wid = tid >> 5, lane = tid & 31;
    const int bm = blockIdx.y * 128, bn = blockIdx.x * 128;

    if (tid < 128) bfs[tid] = bias[bn + tid] * F[bn + tid];

    const char* gA = (const char*)A16 + (size_t)bm * 2048;
    const char* gB = (const char*)B16 + (size_t)bn * 2048;

    auto load_stage = [&](int s) {
        uint32_t st = sb + (uint32_t)(s & 1) * ST2_B;
        size_t kb = (size_t)s * 128;   // 64 elems * 2B
#pragma unroll
        for (int it = 0; it < 4; it++) {
            int i = it * 256 + tid;    // 0..1023
            int r = i >> 3, c = i & 7;
            uint32_t off = (uint32_t)(r * (LDE2 * 2) + c * 16);
            size_t g = (size_t)r * 2048 + kb + c * 16;
            cp16(st + 0 * TILE2_B + off, gA + g);
            cp16(st + 1 * TILE2_B + off, gB + g);
        }
    };

    float acc[16][4];
#pragma unroll
    for (int i = 0; i < 16; i++)
#pragma unroll
        for (int j = 0; j < 4; j++) acc[i][j] = 0.f;

    const int warp_m = (wid >> 2) * 64;
    const int warp_n = (wid & 3) * 32;
    const uint32_t a_row = warp_m + (lane & 15);
    const uint32_t a_k8  = (lane >> 4) * 8;
    const uint32_t b_row = warp_n + (lane & 7);
    const uint32_t b_k8  = ((lane >> 3) & 1) * 8;

    load_stage(0);
    CP_COMMIT();

    for (int s = 0; s < KST2; s++) {
        if (s + 1 < KST2) {
            load_stage(s + 1);
            CP_COMMIT();
            CP_WAIT(1);
        } else {
            CP_WAIT(0);
        }
        __syncthreads();

        uint32_t st = sb + (uint32_t)(s & 1) * ST2_B;
#pragma unroll
        for (int kk = 0; kk < 64; kk += 16) {
            uint32_t ah[4][4], bh[4][2];
#pragma unroll
            for (int mi = 0; mi < 4; mi++) {
                uint32_t ao = ((a_row + mi * 16) * LDE2 + kk + a_k8) * 2;
                ldsm4(ah[mi], st + 0 * TILE2_B + ao);
            }
#pragma unroll
            for (int ni = 0; ni < 4; ni++) {
                uint32_t bo = ((b_row + ni * 8) * LDE2 + kk + b_k8) * 2;
                ldsm2(bh[ni], st + 1 * TILE2_B + bo);
            }
#pragma unroll
            for (int mi = 0; mi < 4; mi++)
#pragma unroll
                for (int ni = 0; ni < 4; ni++)
                    mma_f16(acc[mi * 4 + ni], ah[mi], bh[ni]);
        }
        __syncthreads();
    }

    const int rbase = warp_m + (lane >> 2);
    const int cbase = warp_n + (lane & 3) * 2;
#pragma unroll
    for (int mi = 0; mi < 4; mi++)
#pragma unroll
        for (int ni = 0; ni < 4; ni++) {
            const float* a4 = acc[mi * 4 + ni];
            int c = cbase + ni * 8;
            float bf0 = bfs[c], bf1 = bfs[c + 1];
            int r0 = bm + rbase + mi * 16;
            float v0 = a4[0] + bf0, v1 = a4[1] + bf1;
            float v2 = a4[2] + bf0, v3 = a4[3] + bf1;
            if (C16) {
                *reinterpret_cast<uint32_t*>(&C16[(size_t)r0 * H + bn + c]) = pack_h2(v0, v1);
                *reinterpret_cast<uint32_t*>(&C16[(size_t)(r0 + 8) * H + bn + c]) = pack_h2(v2, v3);
            } else {
                *(float2*)&Cf[(size_t)r0 * H + bn + c] = make_float2(v0, v1);
                *(float2*)&Cf[(size_t)(r0 + 8) * H + bn + c] = make_float2(v2, v3);
            }
        }
}

// ---------------- Flash attention: S bf16 3-pass, PV fp16 1-pass ----------------
#define ALD 144
#define ATILE (128 * ALD)            // 18432
#define AQ_H 0
#define AQ_L ATILE
#define AST_BASE (2 * ATILE)
#define AST_SZ (3 * ATILE)           // kh, kl, v16
#define AK_H 0
#define AK_L ATILE
#define AV16 (2 * ATILE)
#define ATT_SMEM (2 * ATILE + 2 * AST_SZ)   // 147456

__global__ __launch_bounds__(256, 1) void attn_tc(
    const __nv_bfloat16* __restrict__ Qh, const __nv_bfloat16* __restrict__ Ql,
    const __nv_bfloat16* __restrict__ Kh, const __nv_bfloat16* __restrict__ Kl,
    const __half* __restrict__ V16, __half* __restrict__ C16)
{
    char* smem = (char*)smf;
    const uint32_t sb = smem_u32(smem);
    const int tid = threadIdx.x, wid = tid >> 5, lane = tid & 31;
    const int qt = blockIdx.x, hh = blockIdx.y, b = blockIdx.z;
    const int lane4 = lane & 3, laneR = lane >> 2;

    const size_t hbyte = (size_t)hh * HD * 2;

    auto load_q = [&]() {
#pragma unroll
        for (int t = 0; t < 4; t++) {
            int i = t * 256 + tid;
            int r = i >> 3, c = i & 7;
            size_t g = ((size_t)(b * 1024 + qt * 128 + r)) * 2048 + hbyte + c * 16;
            uint32_t off = (uint32_t)(r * ALD + c * 16);
            cp16(sb + AQ_H + off, (const char*)Qh + g);
            cp16(sb + AQ_L + off, (const char*)Ql + g);
        }
    };
    auto load_kv = [&](int kt) {
        uint32_t st = sb + AST_BASE + (uint32_t)(kt & 1) * AST_SZ;
#pragma unroll
        for (int t = 0; t < 4; t++) {
            int i = t * 256 + tid;
            int r = i >> 3, c = i & 7;
            size_t g = ((size_t)(b * 1024 + kt * 128 + r)) * 2048 + hbyte + c * 16;
            uint32_t off = (uint32_t)(r * ALD + c * 16);
            cp16(st + AK_H + off, (const char*)Kh + g);
            cp16(st + AK_L + off, (const char*)Kl + g);
            cp16(st + AV16 + off, (const char*)V16 + g);
        }
    };

    load_q();
    load_kv(0);
    CP_COMMIT();

    uint32_t qhf[4][4], qlf[4][4];
    float o_acc[8][4];
#pragma unroll
    for (int i = 0; i < 8; i++)
#pragma unroll
        for (int j = 0; j < 4; j++) o_acc[i][j] = 0.f;
    float m0 = -1.0e30f, m1 = -1.0e30f, l0 = 0.f, l1 = 0.f;

    for (int kt = 0; kt < 8; kt++) {
        if (kt + 1 < 8) {
            load_kv(kt + 1);
            CP_COMMIT();
            CP_WAIT(1);
        } else {
            CP_WAIT(0);
        }
        __syncthreads();

        if (kt == 0) {
            uint32_t qoff = (uint32_t)((wid * 16 + (lane & 15)) * ALD + ((lane >> 4) * 8) * 2);
#pragma unroll
            for (int kc = 0; kc < 4; kc++) {
                ldsm4(qhf[kc], sb + AQ_H + qoff + kc * 32);
                ldsm4(qlf[kc], sb + AQ_L + qoff + kc * 32);
            }
        }

        uint32_t st = sb + AST_BASE + (uint32_t)(kt & 1) * AST_SZ;

        // ---- S = Q K^T (bf16 3-pass) ----
        float s_acc[16][4];
#pragma unroll
        for (int j = 0; j < 16; j++)
#pragma unroll
            for (int q = 0; q < 4; q++) s_acc[j][q] = 0.f;

        uint32_t kbase = st + (uint32_t)((lane & 7) * ALD + (((lane >> 3) & 1) * 8) * 2);
#pragma unroll
        for (int j = 0; j < 16; j++) {
            uint32_t krow = kbase + (uint32_t)(j * 8 * ALD);
#pragma unroll
            for (int kc = 0; kc < 4; kc++) {
                uint32_t kh2[2], kl2[2];
                ldsm2(kh2, AK_H + krow + kc * 32);
                ldsm2(kl2, AK_L + krow + kc * 32);
                mma_bf(s_acc[j], qhf[kc], kh2);
                mma_bf(s_acc[j], qhf[kc], kl2);
                mma_bf(s_acc[j], qlf[kc], kh2);
            }
        }

        // ---- online softmax ----
        float mx0 = -1.0e30f, mx1 = -1.0e30f;
#pragma unroll
        for (int j = 0; j < 16; j++) {
            s_acc[j][0] *= 0.125f; s_acc[j][1] *= 0.125f;
            s_acc[j][2] *= 0.125f; s_acc[j][3] *= 0.125f;
            mx0 = fmaxf(mx0, fmaxf(s_acc[j][0], s_acc[j][1]));
            mx1 = fmaxf(mx1, fmaxf(s_acc[j][2], s_acc[j][3]));
        }
        mx0 = fmaxf(mx0, __shfl_xor_sync(0xffffffffu, mx0, 1));
        mx0 = fmaxf(mx0, __shfl_xor_sync(0xffffffffu, mx0, 2));
        mx1 = fmaxf(mx1, __shfl_xor_sync(0xffffffffu, mx1, 1));
        mx1 = fmaxf(mx1, __shfl_xor_sync(0xffffffffu, mx1, 2));
        float mn0 = fmaxf(m0, mx0), mn1 = fmaxf(m1, mx1);
        float cr0 = __expf(m0 - mn0), cr1 = __expf(m1 - mn1);
        float rs0 = 0.f, rs1 = 0.f;
#pragma unroll
        for (int j = 0; j < 16; j++) {
            float p0 = __expf(s_acc[j][0] - mn0);
            float p1 = __expf(s_acc[j][1] - mn0);
            float p2 = __expf(s_acc[j][2] - mn1);
            float p3 = __expf(s_acc[j][3] - mn1);
            s_acc[j][0] = p0; s_acc[j][1] = p1; s_acc[j][2] = p2; s_acc[j][3] = p3;
            rs0 += p0 + p1; rs1 += p2 + p3;
        }
        rs0 += __shfl_xor_sync(0xffffffffu, rs0, 1);
        rs0 += __shfl_xor_sync(0xffffffffu, rs0, 2);
        rs1 += __shfl_xor_sync(0xffffffffu, rs1, 1);
        rs1 += __shfl_xor_sync(0xffffffffu, rs1, 2);
        l0 = l0 * cr0 + rs0; m0 = mn0;
        l1 = l1 * cr1 + rs1; m1 = mn1;
#pragma unroll
        for (int nt = 0; nt < 8; nt++) {
            o_acc[nt][0] *= cr0; o_acc[nt][1] *= cr0;
            o_acc[nt][2] *= cr1; o_acc[nt][3] *= cr1;
        }

        // ---- O += P V (fp16 1-pass) ----
        uint32_t vbase = st + (uint32_t)((lane & 15) * ALD);
#pragma unroll
        for (int kc = 0; kc < 8; kc++) {
            uint32_t ph[4];
            ph[0] = pack_h2(s_acc[2 * kc][0], s_acc[2 * kc][1]);
            ph[1] = pack_h2(s_acc[2 * kc][2], s_acc[2 * kc][3]);
            ph[2] = pack_h2(s_acc[2 * kc + 1][0], s_acc[2 * kc + 1][1]);
            ph[3] = pack_h2(s_acc[2 * kc + 1][2], s_acc[2 * kc + 1][3]);
            uint32_t vrow = vbase + (uint32_t)(kc * 16 * ALD);
#pragma unroll
            for (int nt = 0; nt < 8; nt++) {
                uint32_t v2[2];
                ldsm2t(v2, AV16 + vrow + nt * 16);
                mma_f16(o_acc[nt], ph, v2);
            }
        }
        __syncthreads();
    }

    // ---- normalize + write ctx fp16 ----
    float inv0 = 1.0f / l0, inv1 = 1.0f / l1;
    size_t row0 = (size_t)(b * 1024 + qt * 128 + wid * 16 + laneR);
    size_t col = (size_t)hh * HD + lane4 * 2;
#pragma unroll
    for (int nt = 0; nt < 8; nt++) {
        size_t o0 = row0 * H + col + nt * 8;
        size_t o1 = (row0 + 8) * H + col + nt * 8;
        *reinterpret_cast<uint32_t*>(&C16[o0]) =
            pack_h2(o_acc[nt][0] * inv0, o_acc[nt][1] * inv0);
        *reinterpret_cast<uint32_t*>(&C16[o1]) =
            pack_h2(o_acc[nt][2] * inv1, o_acc[nt][3] * inv1);
    }
}

// ---------------- launcher ----------------
extern "C" void kernel_launch(void* const* d_in, const int* in_sizes, int n_in,
                              void* d_out, int out_size)
{
    const float* x = (const float*)d_in[0];
    __nv_bfloat16 *wh, *wl, *xh, *xl, *qkh, *qkl;
    __half *w16, *x16, *v16, *c16;
    cudaGetSymbolAddress((void**)&wh, g_wh);
    cudaGetSymbolAddress((void**)&wl, g_wl);
    cudaGetSymbolAddress((void**)&w16, g_w16);
    cudaGetSymbolAddress((void**)&xh, g_xh);
    cudaGetSymbolAddress((void**)&xl, g_xl);
    cudaGetSymbolAddress((void**)&x16, g_x16);
    cudaGetSymbolAddress((void**)&qkh, g_qkh);
    cudaGetSymbolAddress((void**)&qkl, g_qkl);
    cudaGetSymbolAddress((void**)&v16, g_v16);
    cudaGetSymbolAddress((void**)&c16, g_c16);

    cudaStreamCaptureStatus cst = cudaStreamCaptureStatusNone;
    cudaError_t qerr = cudaStreamIsCapturing((cudaStream_t)0, &cst);
    if (qerr != cudaSuccess || cst != cudaStreamCaptureStatusActive) {
        cudaFuncSetAttribute(gemm_bf,
                             cudaFuncAttributeMaxDynamicSharedMemorySize, GEMM_SMEM);
        cudaFuncSetAttribute(gemm_f16,
                             cudaFuncAttributeMaxDynamicSharedMemorySize, GEMM16_SMEM);
        cudaFuncSetAttribute(attn_tc,
                             cudaFuncAttributeMaxDynamicSharedMemorySize, ATT_SMEM);
    }

    // fused recon: p=0,1 (q,k) -> bf16 pair; p=2,3 (v,o) -> fp16
    ReconArgs ra;
    for (int p = 0; p < 4; p++) {
        ra.W[p]  = (const float*)d_in[1 + p * 5 + 0];
        ra.LM[p] = (const float*)d_in[1 + p * 5 + 2];
        ra.RM[p] = (const float*)d_in[1 + p * 5 + 3];
        ra.F[p]  = (const float*)d_in[1 + p * 5 + 4];
    }
    ra.wh[0] = wh; ra.wh[1] = wh + (size_t)HH;
    ra.wl[0] = wl; ra.wl[1] = wl + (size_t)HH;
    ra.w16[0] = w16; ra.w16[1] = w16 + (size_t)HH;
    recon_all<<<dim3(4, 64, 4), 256>>>(ra);

    split_kernel<<<(NTOK * H) / 1024, 256>>>(x, xh, xl, x16);

    dim3 gg(8, 128);
    // q, k: bf16 3-pass -> bf16 pairs
    for (int p = 0; p < 2; p++) {
        gemm_bf<<<gg, 256, GEMM_SMEM>>>(
            xh, xl, wh + (size_t)p * HH, wl + (size_t)p * HH,
            (const float*)d_in[1 + p * 5 + 1], (const float*)d_in[1 + p * 5 + 4],
            qkh + (size_t)p * NTOK * H, qkl + (size_t)p * NTOK * H);
    }
    // v: fp16 1-pass -> fp16
    gemm_f16<<<gg, 256, GEMM16_SMEM>>>(
        x16, w16,
        (const float*)d_in[1 + 2 * 5 + 1], (const float*)d_in[1 + 2 * 5 + 4],
        nullptr, v16);

    attn_tc<<<dim3(8, NH, 16), 256, ATT_SMEM>>>(
        qkh, qkl, qkh + (size_t)NTOK * H, qkl + (size_t)NTOK * H, v16, c16);

    // o: fp16 1-pass -> fp32 out
    gemm_f16<<<gg, 256, GEMM16_SMEM>>>(
        c16, w16 + (size_t)HH,
        (const float*)d_in[1 + 3 * 5 + 1], (const float*)d_in[1 + 3 * 5 + 4],
        (float*)d_out, nullptr);
}